// round 2
// baseline (speedup 1.0000x reference)
#include <cuda_runtime.h>
#include <cuda_bf16.h>
#include <math.h>

#define NN 30000
#define EE 240000
#define GG 1500
#define EMB 300
#define EMB2 600
#define TASKS 12
#define GAMMA 0.4f
#define INV_T 5.0f   // 1 / T_CON

// ---------------- scratch (static device allocations only) ----------------
__device__ float d_xfeat[NN * EMB];
__device__ float d_hb[NN * EMB];     // enc stack state (h_node)
__device__ float d_xr[NN * EMB];     // rat stack state
__device__ float d_agg[NN * EMB];
__device__ float d_tmp[NN * EMB2];   // reused for pred MLP hidden (3000*600 fits)
__device__ float d_gate[NN];
__device__ float d_hr[GG * EMB];
__device__ float d_henv[GG * EMB];
__device__ float d_hout[GG * EMB];
__device__ float d_henvT[EMB * GG];
__device__ float d_S[GG * GG];
__device__ float d_na[GG], d_nb[GG], d_nc[GG], d_posdot[GG];
__device__ float d_rnum[GG], d_envnum[GG];
__device__ float d_rowsum[GG];
__device__ float d_hin[2 * GG * EMB];

// ---------------- node encoder: out = x[N,9] @ W[9,300] + b ----------------
__global__ void enc_kernel(const float* __restrict__ x, const float* __restrict__ W,
                           const float* __restrict__ b, float* __restrict__ out) {
    int idx = blockIdx.x * blockDim.x + threadIdx.x;
    if (idx >= NN * EMB) return;
    int i = idx / EMB, j = idx % EMB;
    const float* xr = x + i * 9;
    float acc = b[j];
#pragma unroll
    for (int k = 0; k < 9; k++) acc += xr[k] * W[k * EMB + j];
    out[idx] = acc;
}

// ------------- edge message passing: agg[dst] += relu(x[src] + ea@We + be) -------------
// one warp per edge; agg pre-seeded with x (so later (agg+x) is just agg)
__global__ void edge_mp(const float* __restrict__ x, float* __restrict__ agg,
                        const int* __restrict__ src, const int* __restrict__ dst,
                        const float* __restrict__ ea, const float* __restrict__ We,
                        const float* __restrict__ be) {
    int w = (blockIdx.x * blockDim.x + threadIdx.x) >> 5;
    int lane = threadIdx.x & 31;
    if (w >= EE) return;
    int s = src[w], d = dst[w];
    float a0 = ea[w * 3 + 0], a1 = ea[w * 3 + 1], a2 = ea[w * 3 + 2];
    const float* xs = x + (size_t)s * EMB;
    float* ag = agg + (size_t)d * EMB;
    for (int k = lane; k < EMB; k += 32) {
        float e = fmaf(a0, We[k], fmaf(a1, We[EMB + k], fmaf(a2, We[2 * EMB + k], be[k])));
        float m = xs[k] + e;
        m = m > 0.f ? m : 0.f;
        atomicAdd(&ag[k], m);
    }
}

// ---------------- generic SGEMM C[M,N] = A[M,K] @ B[K,N], epilogues ----------------
// ep: 0 = +bias, relu ; 1 = +bias, relu, +resid ; 2 = +bias, +resid ; 3 = raw
__global__ __launch_bounds__(256)
void sgemm128(const float* __restrict__ A, const float* __restrict__ B,
              const float* __restrict__ bias, float* __restrict__ C,
              const float* __restrict__ resid, int M, int N, int K, int ep) {
    __shared__ float As[8][128];
    __shared__ float Bs[8][128];
    const int tid = threadIdx.x;
    const int row0 = blockIdx.y * 128;
    const int col0 = blockIdx.x * 128;
    const int tx = tid % 16;
    const int ty = tid / 16;
    float acc[8][8] = {};
    const int arow = tid >> 1;
    const int acol0 = (tid & 1) * 4;
    const int brow = tid >> 5;
    const int bcol0 = (tid & 31) * 4;
    for (int k0 = 0; k0 < K; k0 += 8) {
#pragma unroll
        for (int i = 0; i < 4; i++) {
            int k = k0 + acol0 + i;
            int r = row0 + arow;
            As[acol0 + i][arow] = (r < M && k < K) ? A[(size_t)r * K + k] : 0.f;
        }
#pragma unroll
        for (int i = 0; i < 4; i++) {
            int c = col0 + bcol0 + i;
            int k = k0 + brow;
            Bs[brow][bcol0 + i] = (c < N && k < K) ? B[(size_t)k * N + c] : 0.f;
        }
        __syncthreads();
#pragma unroll
        for (int kk = 0; kk < 8; kk++) {
            float a[8], b[8];
#pragma unroll
            for (int i = 0; i < 8; i++) a[i] = As[kk][ty * 8 + i];
#pragma unroll
            for (int j = 0; j < 8; j++) b[j] = Bs[kk][tx * 8 + j];
#pragma unroll
            for (int i = 0; i < 8; i++)
#pragma unroll
                for (int j = 0; j < 8; j++) acc[i][j] = fmaf(a[i], b[j], acc[i][j]);
        }
        __syncthreads();
    }
#pragma unroll
    for (int i = 0; i < 8; i++) {
        int r = row0 + ty * 8 + i;
        if (r >= M) continue;
#pragma unroll
        for (int j = 0; j < 8; j++) {
            int c = col0 + tx * 8 + j;
            if (c >= N) continue;
            float v = acc[i][j];
            if (ep != 3) v += bias[c];
            if (ep == 0 || ep == 1) v = fmaxf(v, 0.f);
            if (ep == 1 || ep == 2) v += resid[(size_t)r * N + c];
            C[(size_t)r * N + c] = v;
        }
    }
}

// ---------------- gate: logits = tmp[N,600] @ Wg2[600,2] + bg2 ; gumbel softmax [:,1] ----------------
__global__ void gate_kernel(const float* __restrict__ tmp, const float* __restrict__ Wg2,
                            const float* __restrict__ bg2, const float* __restrict__ gumbel,
                            float* __restrict__ gate) {
    int w = (blockIdx.x * blockDim.x + threadIdx.x) >> 5;
    int lane = threadIdx.x & 31;
    if (w >= NN) return;
    const float* row = tmp + (size_t)w * EMB2;
    float a0 = 0.f, a1 = 0.f;
    for (int k = lane; k < EMB2; k += 32) {
        float v = row[k];
        a0 = fmaf(v, Wg2[2 * k + 0], a0);
        a1 = fmaf(v, Wg2[2 * k + 1], a1);
    }
    for (int o = 16; o; o >>= 1) {
        a0 += __shfl_down_sync(0xffffffffu, a0, o);
        a1 += __shfl_down_sync(0xffffffffu, a1, o);
    }
    if (lane == 0) {
        float z0 = a0 + bg2[0] + gumbel[2 * w + 0];
        float z1 = a1 + bg2[1] + gumbel[2 * w + 1];
        gate[w] = 1.f / (1.f + expf(z0 - z1));  // softmax[:,1]
    }
}

// ---------------- per-graph segment means (batch is sorted) ----------------
__device__ __forceinline__ int lower_bound_batch(const int* __restrict__ batch, int val) {
    int lo = 0, hi = NN;
    while (lo < hi) {
        int mid = (lo + hi) >> 1;
        if (batch[mid] < val) lo = mid + 1; else hi = mid;
    }
    return lo;
}

__global__ void segment_kernel(const float* __restrict__ hb, const float* __restrict__ gate,
                               const int* __restrict__ batch,
                               float* __restrict__ hr, float* __restrict__ henv,
                               float* __restrict__ hout, float* __restrict__ rnum,
                               float* __restrict__ envnum) {
    int g = blockIdx.x;
    int s = lower_bound_batch(batch, g);
    int e = lower_bound_batch(batch, g + 1);
    float cnt = fmaxf((float)(e - s), 1.f);
    int tid = threadIdx.x;
    if (tid < EMB) {
        float ar = 0.f, ae = 0.f, ao = 0.f;
        for (int n = s; n < e; n++) {
            float h = hb[(size_t)n * EMB + tid];
            float gt = gate[n];
            ar = fmaf(gt, h, ar);
            ae = fmaf(1.f - gt, h, ae);
            ao += h;
        }
        hr[g * EMB + tid] = ar / cnt;
        henv[g * EMB + tid] = ae / cnt;
        hout[g * EMB + tid] = ao / cnt;
    }
    __shared__ float sh[512];
    float gs = 0.f;
    for (int n = s + tid; n < e; n += blockDim.x) gs += gate[n];
    sh[tid] = gs;
    __syncthreads();
    for (int o = 256; o; o >>= 1) {
        if (tid < o) sh[tid] += sh[tid + o];
        __syncthreads();
    }
    if (tid == 0) {
        rnum[g] = sh[0] + 1e-8f;
        envnum[g] = ((float)(e - s) - sh[0]) + 1e-8f;
    }
}

// ---------------- per-graph norms + diagonal dot ----------------
__global__ void norm_kernel(const float* __restrict__ hr, const float* __restrict__ henv,
                            const float* __restrict__ hout, float* __restrict__ na,
                            float* __restrict__ nb, float* __restrict__ nc,
                            float* __restrict__ posdot) {
    int g = blockIdx.x, tid = threadIdx.x;  // 128 threads
    float s1 = 0, s2 = 0, s3 = 0, s4 = 0;
    for (int d = tid; d < EMB; d += 128) {
        float a = hr[g * EMB + d], o = hout[g * EMB + d], ev = henv[g * EMB + d];
        s1 = fmaf(a, a, s1); s2 = fmaf(o, o, s2); s3 = fmaf(ev, ev, s3); s4 = fmaf(a, o, s4);
    }
    __shared__ float sh[128];
    auto red = [&](float v) -> float {
        sh[tid] = v; __syncthreads();
        for (int o = 64; o; o >>= 1) { if (tid < o) sh[tid] += sh[tid + o]; __syncthreads(); }
        float r = sh[0]; __syncthreads();
        return r;
    };
    float r1 = red(s1), r2 = red(s2), r3 = red(s3), r4 = red(s4);
    if (tid == 0) {
        na[g] = sqrtf(r1); nb[g] = sqrtf(r2); nc[g] = sqrtf(r3); posdot[g] = r4;
    }
}

__global__ void lossreg_kernel(const float* __restrict__ rnum, const float* __restrict__ envnum,
                               float* __restrict__ out) {
    int tid = threadIdx.x;
    float local = 0.f;
    for (int g = tid; g < GG; g += 512) {
        float r = rnum[g], ev = envnum[g];
        local += fabsf(r / (r + ev) - GAMMA);
    }
    __shared__ float sh[512];
    sh[tid] = local; __syncthreads();
    for (int o = 256; o; o >>= 1) { if (tid < o) sh[tid] += sh[tid + o]; __syncthreads(); }
    if (tid == 0) out[0] = sh[0] / (float)GG;
}

__global__ void transpose_kernel(const float* __restrict__ henv, float* __restrict__ henvT) {
    int idx = blockIdx.x * blockDim.x + threadIdx.x;
    if (idx >= GG * EMB) return;
    int g = idx / EMB, d = idx % EMB;
    henvT[d * GG + g] = henv[idx];
}

__global__ void rowsum_kernel(const float* __restrict__ S, const float* __restrict__ na,
                              const float* __restrict__ nc, float* __restrict__ rowsum) {
    int g = blockIdx.x, tid = threadIdx.x;  // 256 threads
    float nag = na[g];
    float local = 0.f;
    for (int j = tid; j < GG; j += 256) {
        float denom = nag * nc[j] + 1e-8f;
        local += expf(S[(size_t)g * GG + j] / denom * INV_T);
    }
    __shared__ float sh[256];
    sh[tid] = local; __syncthreads();
    for (int o = 128; o; o >>= 1) { if (tid < o) sh[tid] += sh[tid + o]; __syncthreads(); }
    if (tid == 0) rowsum[g] = sh[0];
}

__global__ void losscon_kernel(const float* __restrict__ posdot, const float* __restrict__ na,
                               const float* __restrict__ nb, const float* __restrict__ rowsum,
                               float* __restrict__ out) {
    int tid = threadIdx.x;
    float local = 0.f;
    for (int g = tid; g < GG; g += 512) {
        float pos = expf(posdot[g] / (na[g] * nb[g] + 1e-8f) * INV_T);
        local += -logf(pos / (rowsum[g] + pos));
    }
    __shared__ float sh[512];
    sh[tid] = local; __syncthreads();
    for (int o = 256; o; o >>= 1) { if (tid < o) sh[tid] += sh[tid + o]; __syncthreads(); }
    if (tid == 0) out[0] = sh[0] / (float)GG;
}

__global__ void hin_kernel(const float* __restrict__ hr, const float* __restrict__ henv,
                           const int* __restrict__ perm, float* __restrict__ hin) {
    int idx = blockIdx.x * blockDim.x + threadIdx.x;
    if (idx >= GG * EMB) return;
    int g = idx / EMB, d = idx % EMB;
    float r = hr[idx];
    hin[idx] = r + henv[(size_t)perm[g] * EMB + d];  // pred_rep input
    hin[(size_t)(GG + g) * EMB + d] = r;             // pred_rem input
}

// out rows 0..1499 -> pred_rep at out[g*12+t]; rows 1500..2999 -> pred_rem at out[18000+...]
__global__ void pred2_kernel(const float* __restrict__ tmp, const float* __restrict__ Wp2,
                             const float* __restrict__ bp2, float* __restrict__ out) {
    int idx = blockIdx.x * blockDim.x + threadIdx.x;
    if (idx >= 2 * GG * TASKS) return;
    int row = idx / TASKS, t = idx % TASKS;
    const float* r = tmp + (size_t)row * EMB2;
    float acc = bp2[t];
    for (int k = 0; k < EMB2; k++) acc = fmaf(r[k], Wp2[k * TASKS + t], acc);
    int o = (row < GG) ? (row * TASKS + t) : (GG * TASKS + (row - GG) * TASKS + t);
    out[o] = acc;
}

// =====================================================================================
extern "C" void kernel_launch(void* const* d_in, const int* in_sizes, int n_in,
                              void* d_out, int out_size) {
    const float* x         = (const float*)d_in[0];
    const float* edge_attr = (const float*)d_in[1];
    const int*   edge_index= (const int*)  d_in[2];
    const int*   batch     = (const int*)  d_in[3];
    const float* gumbel    = (const float*)d_in[4];
    const int*   perm      = (const int*)  d_in[5];
    const float* W_enc = (const float*)d_in[6];
    const float* b_enc = (const float*)d_in[7];
    const float* We_g  = (const float*)d_in[8];
    const float* be_g  = (const float*)d_in[9];
    const float* W1_g  = (const float*)d_in[10];
    const float* b1_g  = (const float*)d_in[11];
    const float* W2_g  = (const float*)d_in[12];
    const float* b2_g  = (const float*)d_in[13];
    const float* We_r  = (const float*)d_in[14];
    const float* be_r  = (const float*)d_in[15];
    const float* W1_r  = (const float*)d_in[16];
    const float* b1_r  = (const float*)d_in[17];
    const float* W2_r  = (const float*)d_in[18];
    const float* b2_r  = (const float*)d_in[19];
    const float* Wg1   = (const float*)d_in[20];
    const float* bg1   = (const float*)d_in[21];
    const float* Wg2   = (const float*)d_in[22];
    const float* bg2   = (const float*)d_in[23];
    const float* Wp1   = (const float*)d_in[24];
    const float* bp1   = (const float*)d_in[25];
    const float* Wp2   = (const float*)d_in[26];
    const float* bp2   = (const float*)d_in[27];
    float* out = (float*)d_out;

    const int* src = edge_index;
    const int* dst = edge_index + EE;

    float *xfeat, *hb, *xr, *agg, *tmp, *gate, *hr, *henv, *hout, *henvT, *S;
    float *na, *nb, *nc, *posdot, *rnum, *envnum, *rowsum, *hin;
    cudaGetSymbolAddress((void**)&xfeat, d_xfeat);
    cudaGetSymbolAddress((void**)&hb, d_hb);
    cudaGetSymbolAddress((void**)&xr, d_xr);
    cudaGetSymbolAddress((void**)&agg, d_agg);
    cudaGetSymbolAddress((void**)&tmp, d_tmp);
    cudaGetSymbolAddress((void**)&gate, d_gate);
    cudaGetSymbolAddress((void**)&hr, d_hr);
    cudaGetSymbolAddress((void**)&henv, d_henv);
    cudaGetSymbolAddress((void**)&hout, d_hout);
    cudaGetSymbolAddress((void**)&henvT, d_henvT);
    cudaGetSymbolAddress((void**)&S, d_S);
    cudaGetSymbolAddress((void**)&na, d_na);
    cudaGetSymbolAddress((void**)&nb, d_nb);
    cudaGetSymbolAddress((void**)&nc, d_nc);
    cudaGetSymbolAddress((void**)&posdot, d_posdot);
    cudaGetSymbolAddress((void**)&rnum, d_rnum);
    cudaGetSymbolAddress((void**)&envnum, d_envnum);
    cudaGetSymbolAddress((void**)&rowsum, d_rowsum);
    cudaGetSymbolAddress((void**)&hin, d_hin);

    const size_t rowBytes = (size_t)NN * EMB * sizeof(float);

    // node encoder
    enc_kernel<<<(NN * EMB + 255) / 256, 256>>>(x, W_enc, b_enc, xfeat);
    cudaMemcpyAsync(hb, xfeat, rowBytes, cudaMemcpyDeviceToDevice);
    cudaMemcpyAsync(xr, xfeat, rowBytes, cudaMemcpyDeviceToDevice);

    dim3 gridMM1((EMB2 + 127) / 128, (NN + 127) / 128);  // N=600
    dim3 gridMM2((EMB + 127) / 128, (NN + 127) / 128);   // N=300
    const int edgeBlocks = (EE + 7) / 8;  // 8 warps / 256-thread block

    // enc GIN stack (L=5)
    for (int l = 0; l < 5; l++) {
        cudaMemcpyAsync(agg, hb, rowBytes, cudaMemcpyDeviceToDevice);
        edge_mp<<<edgeBlocks, 256>>>(hb, agg, src, dst, edge_attr,
                                     We_g + l * 3 * EMB, be_g + l * EMB);
        sgemm128<<<gridMM1, 256>>>(agg, W1_g + (size_t)l * EMB * EMB2, b1_g + l * EMB2,
                                   tmp, nullptr, NN, EMB2, EMB, 0);
        sgemm128<<<gridMM2, 256>>>(tmp, W2_g + (size_t)l * EMB2 * EMB, b2_g + l * EMB,
                                   hb, hb, NN, EMB, EMB2, (l < 4) ? 1 : 2);
    }
    // rat GIN stack (L=2)
    for (int l = 0; l < 2; l++) {
        cudaMemcpyAsync(agg, xr, rowBytes, cudaMemcpyDeviceToDevice);
        edge_mp<<<edgeBlocks, 256>>>(xr, agg, src, dst, edge_attr,
                                     We_r + l * 3 * EMB, be_r + l * EMB);
        sgemm128<<<gridMM1, 256>>>(agg, W1_r + (size_t)l * EMB * EMB2, b1_r + l * EMB2,
                                   tmp, nullptr, NN, EMB2, EMB, 0);
        sgemm128<<<gridMM2, 256>>>(tmp, W2_r + (size_t)l * EMB2 * EMB, b2_r + l * EMB,
                                   xr, xr, NN, EMB, EMB2, (l < 1) ? 1 : 2);
    }

    // gate
    sgemm128<<<gridMM1, 256>>>(xr, Wg1, bg1, tmp, nullptr, NN, EMB2, EMB, 0);
    gate_kernel<<<(NN * 32 + 255) / 256, 256>>>(tmp, Wg2, bg2, gumbel, gate);

    // per-graph reductions
    segment_kernel<<<GG, 512>>>(hb, gate, batch, hr, henv, hout, rnum, envnum);
    norm_kernel<<<GG, 128>>>(hr, henv, hout, na, nb, nc, posdot);
    lossreg_kernel<<<1, 512>>>(rnum, envnum, out + 2 * GG * TASKS);

    // contrastive loss: S = hr @ henv^T
    transpose_kernel<<<(GG * EMB + 255) / 256, 256>>>(henv, henvT);
    dim3 gridS((GG + 127) / 128, (GG + 127) / 128);
    sgemm128<<<gridS, 256>>>(hr, henvT, nullptr, S, nullptr, GG, GG, EMB, 3);
    rowsum_kernel<<<GG, 256>>>(S, na, nc, rowsum);
    losscon_kernel<<<1, 512>>>(posdot, na, nb, rowsum, out + 2 * GG * TASKS + 1);

    // prediction MLPs (batched: rows [0,1500)=rep input, [1500,3000)=rem input)
    hin_kernel<<<(GG * EMB + 255) / 256, 256>>>(hr, henv, perm, hin);
    dim3 gridP((EMB2 + 127) / 128, (2 * GG + 127) / 128);
    sgemm128<<<gridP, 256>>>(hin, Wp1, bp1, tmp, nullptr, 2 * GG, EMB2, EMB, 0);
    pred2_kernel<<<(2 * GG * TASKS + 127) / 128, 128>>>(tmp, Wp2, bp2, out);
}

// round 3
// speedup vs baseline: 1.2023x; 1.2023x over previous
#include <cuda_runtime.h>
#include <cuda_bf16.h>
#include <math.h>

#define NN 30000
#define EE 240000
#define GG 1500
#define EMB 300
#define EMB2 600
#define TASKS 12
#define GAMMA 0.4f
#define INV_T 5.0f   // 1 / T_CON

// ---------------- scratch (static device allocations only) ----------------
__device__ float d_xfeat[NN * EMB];
__device__ float d_hb[NN * EMB];     // enc stack state (h_node)
__device__ float d_xr[NN * EMB];     // rat stack state
__device__ float d_agg[NN * EMB];
__device__ float d_tmp[NN * EMB2];   // reused for pred MLP hidden
__device__ float d_gate[NN];
__device__ float d_hr[GG * EMB];
__device__ float d_henv[GG * EMB];
__device__ float d_hout[GG * EMB];
__device__ float d_henvT[EMB * GG];
__device__ float d_S[GG * GG];
__device__ float d_na[GG], d_nb[GG], d_nc[GG], d_posdot[GG];
__device__ float d_rnum[GG], d_envnum[GG];
__device__ float d_rowsum[GG];
__device__ float d_hin[2 * GG * EMB];

// ---------------- node encoder: out = x[N,9] @ W[9,300] + b ----------------
__global__ void enc_kernel(const float* __restrict__ x, const float* __restrict__ W,
                           const float* __restrict__ b, float* __restrict__ out) {
    int idx = blockIdx.x * blockDim.x + threadIdx.x;
    if (idx >= NN * EMB) return;
    int i = idx / EMB, j = idx % EMB;
    const float* xr = x + i * 9;
    float acc = b[j];
#pragma unroll
    for (int k = 0; k < 9; k++) acc += xr[k] * W[k * EMB + j];
    out[idx] = acc;
}

// ------------- edge message passing: agg[dst] += relu(x[src] + ea@We + be) -------------
__global__ void edge_mp(const float* __restrict__ x, float* __restrict__ agg,
                        const int* __restrict__ src, const int* __restrict__ dst,
                        const float* __restrict__ ea, const float* __restrict__ We,
                        const float* __restrict__ be) {
    int w = (blockIdx.x * blockDim.x + threadIdx.x) >> 5;
    int lane = threadIdx.x & 31;
    if (w >= EE) return;
    int s = src[w], d = dst[w];
    float a0 = ea[w * 3 + 0], a1 = ea[w * 3 + 1], a2 = ea[w * 3 + 2];
    const float* xs = x + (size_t)s * EMB;
    float* ag = agg + (size_t)d * EMB;
    for (int k = lane; k < EMB; k += 32) {
        float e = fmaf(a0, We[k], fmaf(a1, We[EMB + k], fmaf(a2, We[2 * EMB + k], be[k])));
        float m = xs[k] + e;
        m = m > 0.f ? m : 0.f;
        atomicAdd(&ag[k], m);
    }
}

// ---------------- optimized SGEMM: 128x128x16 double-buffered, float4 ----------------
// ep: 0 = +bias, relu ; 1 = +bias, relu, +resid ; 2 = +bias, +resid ; 3 = raw
#define BM 128
#define BN 128
#define BK 16
__global__ __launch_bounds__(256, 2)
void sgemm_opt(const float* __restrict__ A, const float* __restrict__ B,
               const float* __restrict__ bias, float* __restrict__ C,
               const float* __restrict__ resid, int M, int N, int K, int ep) {
    __shared__ float As[2][BK][BM + 4];
    __shared__ float Bs[2][BK][BN];

    const int tid = threadIdx.x;
    const int row0 = blockIdx.y * BM;
    const int col0 = blockIdx.x * BN;
    const int tx = tid & 15;       // 0..15 -> 8 cols each
    const int ty = tid >> 4;       // 0..15 -> 8 rows each

    // A loading: thread handles row ar, k-span [ak0, ak0+8)
    const int ar = tid >> 1;
    const int ak0 = (tid & 1) * 8;
    // B loading: thread handles rows br, br+8, col-span [bc, bc+4)
    const int br = tid >> 5;
    const int bc = (tid & 31) * 4;

    float4 aReg[2], bReg[2];

    const int gr = row0 + ar;
    const bool arow_ok = (gr < M);
    const float* Arow = A + (size_t)gr * K;

    auto loadA = [&](int k0) {
#pragma unroll
        for (int v = 0; v < 2; v++) {
            int k = k0 + ak0 + v * 4;
            float4 t = make_float4(0.f, 0.f, 0.f, 0.f);
            if (arow_ok) {
                if (k + 3 < K) {
                    t = *(const float4*)(Arow + k);
                } else {
                    float u[4] = {0.f, 0.f, 0.f, 0.f};
#pragma unroll
                    for (int q = 0; q < 4; q++) if (k + q < K) u[q] = Arow[k + q];
                    t = make_float4(u[0], u[1], u[2], u[3]);
                }
            }
            aReg[v] = t;
        }
    };
    auto loadB = [&](int k0) {
#pragma unroll
        for (int v = 0; v < 2; v++) {
            int k = k0 + br + v * 8;
            int c = col0 + bc;
            float4 t = make_float4(0.f, 0.f, 0.f, 0.f);
            if (k < K) {
                const float* Brow = B + (size_t)k * N;
                if (c + 3 < N) {
                    t = *(const float4*)(Brow + c);
                } else {
                    float u[4] = {0.f, 0.f, 0.f, 0.f};
#pragma unroll
                    for (int q = 0; q < 4; q++) if (c + q < N) u[q] = Brow[c + q];
                    t = make_float4(u[0], u[1], u[2], u[3]);
                }
            }
            bReg[v] = t;
        }
    };
    auto storeAB = [&](int buf) {
#pragma unroll
        for (int v = 0; v < 2; v++) {
            As[buf][ak0 + v * 4 + 0][ar] = aReg[v].x;
            As[buf][ak0 + v * 4 + 1][ar] = aReg[v].y;
            As[buf][ak0 + v * 4 + 2][ar] = aReg[v].z;
            As[buf][ak0 + v * 4 + 3][ar] = aReg[v].w;
            *(float4*)&Bs[buf][br + v * 8][bc] = bReg[v];
        }
    };

    float acc[8][8] = {};

    const int nk = (K + BK - 1) / BK;
    loadA(0); loadB(0);
    storeAB(0);
    __syncthreads();

    for (int t = 0; t < nk; t++) {
        const int buf = t & 1;
        if (t + 1 < nk) { loadA((t + 1) * BK); loadB((t + 1) * BK); }
#pragma unroll
        for (int kk = 0; kk < BK; kk++) {
            float a[8], b[8];
            *(float4*)&a[0] = *(const float4*)&As[buf][kk][ty * 8];
            *(float4*)&a[4] = *(const float4*)&As[buf][kk][ty * 8 + 4];
            *(float4*)&b[0] = *(const float4*)&Bs[buf][kk][tx * 8];
            *(float4*)&b[4] = *(const float4*)&Bs[buf][kk][tx * 8 + 4];
#pragma unroll
            for (int i = 0; i < 8; i++)
#pragma unroll
                for (int j = 0; j < 8; j++) acc[i][j] = fmaf(a[i], b[j], acc[i][j]);
        }
        if (t + 1 < nk) {
            storeAB(buf ^ 1);   // other buffer: everyone passed the previous sync
            __syncthreads();
        }
    }

#pragma unroll
    for (int i = 0; i < 8; i++) {
        int r = row0 + ty * 8 + i;
        if (r >= M) continue;
#pragma unroll
        for (int j = 0; j < 8; j++) {
            int c = col0 + tx * 8 + j;
            if (c >= N) continue;
            float v = acc[i][j];
            if (ep != 3) v += bias[c];
            if (ep == 0 || ep == 1) v = fmaxf(v, 0.f);
            if (ep == 1 || ep == 2) v += resid[(size_t)r * N + c];
            C[(size_t)r * N + c] = v;
        }
    }
}

// ---------------- gate: logits = tmp[N,600] @ Wg2[600,2] + bg2 ; gumbel softmax [:,1] ----------------
__global__ void gate_kernel(const float* __restrict__ tmp, const float* __restrict__ Wg2,
                            const float* __restrict__ bg2, const float* __restrict__ gumbel,
                            float* __restrict__ gate) {
    int w = (blockIdx.x * blockDim.x + threadIdx.x) >> 5;
    int lane = threadIdx.x & 31;
    if (w >= NN) return;
    const float* row = tmp + (size_t)w * EMB2;
    float a0 = 0.f, a1 = 0.f;
    for (int k = lane; k < EMB2; k += 32) {
        float v = row[k];
        a0 = fmaf(v, Wg2[2 * k + 0], a0);
        a1 = fmaf(v, Wg2[2 * k + 1], a1);
    }
    for (int o = 16; o; o >>= 1) {
        a0 += __shfl_down_sync(0xffffffffu, a0, o);
        a1 += __shfl_down_sync(0xffffffffu, a1, o);
    }
    if (lane == 0) {
        float z0 = a0 + bg2[0] + gumbel[2 * w + 0];
        float z1 = a1 + bg2[1] + gumbel[2 * w + 1];
        gate[w] = 1.f / (1.f + expf(z0 - z1));
    }
}

// ---------------- per-graph segment means (batch is sorted) ----------------
__device__ __forceinline__ int lower_bound_batch(const int* __restrict__ batch, int val) {
    int lo = 0, hi = NN;
    while (lo < hi) {
        int mid = (lo + hi) >> 1;
        if (batch[mid] < val) lo = mid + 1; else hi = mid;
    }
    return lo;
}

__global__ void segment_kernel(const float* __restrict__ hb, const float* __restrict__ gate,
                               const int* __restrict__ batch,
                               float* __restrict__ hr, float* __restrict__ henv,
                               float* __restrict__ hout, float* __restrict__ rnum,
                               float* __restrict__ envnum) {
    int g = blockIdx.x;
    int s = lower_bound_batch(batch, g);
    int e = lower_bound_batch(batch, g + 1);
    float cnt = fmaxf((float)(e - s), 1.f);
    int tid = threadIdx.x;
    if (tid < EMB) {
        float ar = 0.f, ae = 0.f, ao = 0.f;
        for (int n = s; n < e; n++) {
            float h = hb[(size_t)n * EMB + tid];
            float gt = gate[n];
            ar = fmaf(gt, h, ar);
            ae = fmaf(1.f - gt, h, ae);
            ao += h;
        }
        hr[g * EMB + tid] = ar / cnt;
        henv[g * EMB + tid] = ae / cnt;
        hout[g * EMB + tid] = ao / cnt;
    }
    __shared__ float sh[512];
    float gs = 0.f;
    for (int n = s + tid; n < e; n += blockDim.x) gs += gate[n];
    sh[tid] = gs;
    __syncthreads();
    for (int o = 256; o; o >>= 1) {
        if (tid < o) sh[tid] += sh[tid + o];
        __syncthreads();
    }
    if (tid == 0) {
        rnum[g] = sh[0] + 1e-8f;
        envnum[g] = ((float)(e - s) - sh[0]) + 1e-8f;
    }
}

// ---------------- per-graph norms + diagonal dot ----------------
__global__ void norm_kernel(const float* __restrict__ hr, const float* __restrict__ henv,
                            const float* __restrict__ hout, float* __restrict__ na,
                            float* __restrict__ nb, float* __restrict__ nc,
                            float* __restrict__ posdot) {
    int g = blockIdx.x, tid = threadIdx.x;  // 128 threads
    float s1 = 0, s2 = 0, s3 = 0, s4 = 0;
    for (int d = tid; d < EMB; d += 128) {
        float a = hr[g * EMB + d], o = hout[g * EMB + d], ev = henv[g * EMB + d];
        s1 = fmaf(a, a, s1); s2 = fmaf(o, o, s2); s3 = fmaf(ev, ev, s3); s4 = fmaf(a, o, s4);
    }
    __shared__ float sh[128];
    auto red = [&](float v) -> float {
        sh[tid] = v; __syncthreads();
        for (int o = 64; o; o >>= 1) { if (tid < o) sh[tid] += sh[tid + o]; __syncthreads(); }
        float r = sh[0]; __syncthreads();
        return r;
    };
    float r1 = red(s1), r2 = red(s2), r3 = red(s3), r4 = red(s4);
    if (tid == 0) {
        na[g] = sqrtf(r1); nb[g] = sqrtf(r2); nc[g] = sqrtf(r3); posdot[g] = r4;
    }
}

__global__ void lossreg_kernel(const float* __restrict__ rnum, const float* __restrict__ envnum,
                               float* __restrict__ out) {
    int tid = threadIdx.x;
    float local = 0.f;
    for (int g = tid; g < GG; g += 512) {
        float r = rnum[g], ev = envnum[g];
        local += fabsf(r / (r + ev) - GAMMA);
    }
    __shared__ float sh[512];
    sh[tid] = local; __syncthreads();
    for (int o = 256; o; o >>= 1) { if (tid < o) sh[tid] += sh[tid + o]; __syncthreads(); }
    if (tid == 0) out[0] = sh[0] / (float)GG;
}

__global__ void transpose_kernel(const float* __restrict__ henv, float* __restrict__ henvT) {
    int idx = blockIdx.x * blockDim.x + threadIdx.x;
    if (idx >= GG * EMB) return;
    int g = idx / EMB, d = idx % EMB;
    henvT[d * GG + g] = henv[idx];
}

__global__ void rowsum_kernel(const float* __restrict__ S, const float* __restrict__ na,
                              const float* __restrict__ nc, float* __restrict__ rowsum) {
    int g = blockIdx.x, tid = threadIdx.x;  // 256 threads
    float nag = na[g];
    float local = 0.f;
    for (int j = tid; j < GG; j += 256) {
        float denom = nag * nc[j] + 1e-8f;
        local += expf(S[(size_t)g * GG + j] / denom * INV_T);
    }
    __shared__ float sh[256];
    sh[tid] = local; __syncthreads();
    for (int o = 128; o; o >>= 1) { if (tid < o) sh[tid] += sh[tid + o]; __syncthreads(); }
    if (tid == 0) rowsum[g] = sh[0];
}

__global__ void losscon_kernel(const float* __restrict__ posdot, const float* __restrict__ na,
                               const float* __restrict__ nb, const float* __restrict__ rowsum,
                               float* __restrict__ out) {
    int tid = threadIdx.x;
    float local = 0.f;
    for (int g = tid; g < GG; g += 512) {
        float pos = expf(posdot[g] / (na[g] * nb[g] + 1e-8f) * INV_T);
        local += -logf(pos / (rowsum[g] + pos));
    }
    __shared__ float sh[512];
    sh[tid] = local; __syncthreads();
    for (int o = 256; o; o >>= 1) { if (tid < o) sh[tid] += sh[tid + o]; __syncthreads(); }
    if (tid == 0) out[0] = sh[0] / (float)GG;
}

__global__ void hin_kernel(const float* __restrict__ hr, const float* __restrict__ henv,
                           const int* __restrict__ perm, float* __restrict__ hin) {
    int idx = blockIdx.x * blockDim.x + threadIdx.x;
    if (idx >= GG * EMB) return;
    int g = idx / EMB, d = idx % EMB;
    float r = hr[idx];
    hin[idx] = r + henv[(size_t)perm[g] * EMB + d];
    hin[(size_t)(GG + g) * EMB + d] = r;
}

__global__ void pred2_kernel(const float* __restrict__ tmp, const float* __restrict__ Wp2,
                             const float* __restrict__ bp2, float* __restrict__ out) {
    int idx = blockIdx.x * blockDim.x + threadIdx.x;
    if (idx >= 2 * GG * TASKS) return;
    int row = idx / TASKS, t = idx % TASKS;
    const float* r = tmp + (size_t)row * EMB2;
    float acc = bp2[t];
    for (int k = 0; k < EMB2; k++) acc = fmaf(r[k], Wp2[k * TASKS + t], acc);
    int o = (row < GG) ? (row * TASKS + t) : (GG * TASKS + (row - GG) * TASKS + t);
    out[o] = acc;
}

// =====================================================================================
extern "C" void kernel_launch(void* const* d_in, const int* in_sizes, int n_in,
                              void* d_out, int out_size) {
    const float* x         = (const float*)d_in[0];
    const float* edge_attr = (const float*)d_in[1];
    const int*   edge_index= (const int*)  d_in[2];
    const int*   batch     = (const int*)  d_in[3];
    const float* gumbel    = (const float*)d_in[4];
    const int*   perm      = (const int*)  d_in[5];
    const float* W_enc = (const float*)d_in[6];
    const float* b_enc = (const float*)d_in[7];
    const float* We_g  = (const float*)d_in[8];
    const float* be_g  = (const float*)d_in[9];
    const float* W1_g  = (const float*)d_in[10];
    const float* b1_g  = (const float*)d_in[11];
    const float* W2_g  = (const float*)d_in[12];
    const float* b2_g  = (const float*)d_in[13];
    const float* We_r  = (const float*)d_in[14];
    const float* be_r  = (const float*)d_in[15];
    const float* W1_r  = (const float*)d_in[16];
    const float* b1_r  = (const float*)d_in[17];
    const float* W2_r  = (const float*)d_in[18];
    const float* b2_r  = (const float*)d_in[19];
    const float* Wg1   = (const float*)d_in[20];
    const float* bg1   = (const float*)d_in[21];
    const float* Wg2   = (const float*)d_in[22];
    const float* bg2   = (const float*)d_in[23];
    const float* Wp1   = (const float*)d_in[24];
    const float* bp1   = (const float*)d_in[25];
    const float* Wp2   = (const float*)d_in[26];
    const float* bp2   = (const float*)d_in[27];
    float* out = (float*)d_out;

    const int* src = edge_index;
    const int* dst = edge_index + EE;

    float *xfeat, *hb, *xr, *agg, *tmp, *gate, *hr, *henv, *hout, *henvT, *S;
    float *na, *nb, *nc, *posdot, *rnum, *envnum, *rowsum, *hin;
    cudaGetSymbolAddress((void**)&xfeat, d_xfeat);
    cudaGetSymbolAddress((void**)&hb, d_hb);
    cudaGetSymbolAddress((void**)&xr, d_xr);
    cudaGetSymbolAddress((void**)&agg, d_agg);
    cudaGetSymbolAddress((void**)&tmp, d_tmp);
    cudaGetSymbolAddress((void**)&gate, d_gate);
    cudaGetSymbolAddress((void**)&hr, d_hr);
    cudaGetSymbolAddress((void**)&henv, d_henv);
    cudaGetSymbolAddress((void**)&hout, d_hout);
    cudaGetSymbolAddress((void**)&henvT, d_henvT);
    cudaGetSymbolAddress((void**)&S, d_S);
    cudaGetSymbolAddress((void**)&na, d_na);
    cudaGetSymbolAddress((void**)&nb, d_nb);
    cudaGetSymbolAddress((void**)&nc, d_nc);
    cudaGetSymbolAddress((void**)&posdot, d_posdot);
    cudaGetSymbolAddress((void**)&rnum, d_rnum);
    cudaGetSymbolAddress((void**)&envnum, d_envnum);
    cudaGetSymbolAddress((void**)&rowsum, d_rowsum);
    cudaGetSymbolAddress((void**)&hin, d_hin);

    const size_t rowBytes = (size_t)NN * EMB * sizeof(float);

    enc_kernel<<<(NN * EMB + 255) / 256, 256>>>(x, W_enc, b_enc, xfeat);
    cudaMemcpyAsync(hb, xfeat, rowBytes, cudaMemcpyDeviceToDevice);
    cudaMemcpyAsync(xr, xfeat, rowBytes, cudaMemcpyDeviceToDevice);

    dim3 gridMM1((EMB2 + BN - 1) / BN, (NN + BM - 1) / BM);
    dim3 gridMM2((EMB + BN - 1) / BN, (NN + BM - 1) / BM);
    const int edgeBlocks = (EE + 7) / 8;

    // enc GIN stack (L=5)
    for (int l = 0; l < 5; l++) {
        cudaMemcpyAsync(agg, hb, rowBytes, cudaMemcpyDeviceToDevice);
        edge_mp<<<edgeBlocks, 256>>>(hb, agg, src, dst, edge_attr,
                                     We_g + l * 3 * EMB, be_g + l * EMB);
        sgemm_opt<<<gridMM1, 256>>>(agg, W1_g + (size_t)l * EMB * EMB2, b1_g + l * EMB2,
                                    tmp, nullptr, NN, EMB2, EMB, 0);
        sgemm_opt<<<gridMM2, 256>>>(tmp, W2_g + (size_t)l * EMB2 * EMB, b2_g + l * EMB,
                                    hb, hb, NN, EMB, EMB2, (l < 4) ? 1 : 2);
    }
    // rat GIN stack (L=2)
    for (int l = 0; l < 2; l++) {
        cudaMemcpyAsync(agg, xr, rowBytes, cudaMemcpyDeviceToDevice);
        edge_mp<<<edgeBlocks, 256>>>(xr, agg, src, dst, edge_attr,
                                     We_r + l * 3 * EMB, be_r + l * EMB);
        sgemm_opt<<<gridMM1, 256>>>(agg, W1_r + (size_t)l * EMB * EMB2, b1_r + l * EMB2,
                                    tmp, nullptr, NN, EMB2, EMB, 0);
        sgemm_opt<<<gridMM2, 256>>>(tmp, W2_r + (size_t)l * EMB2 * EMB, b2_r + l * EMB,
                                    xr, xr, NN, EMB, EMB2, (l < 1) ? 1 : 2);
    }

    // gate
    sgemm_opt<<<gridMM1, 256>>>(xr, Wg1, bg1, tmp, nullptr, NN, EMB2, EMB, 0);
    gate_kernel<<<(NN * 32 + 255) / 256, 256>>>(tmp, Wg2, bg2, gumbel, gate);

    // per-graph reductions
    segment_kernel<<<GG, 512>>>(hb, gate, batch, hr, henv, hout, rnum, envnum);
    norm_kernel<<<GG, 128>>>(hr, henv, hout, na, nb, nc, posdot);
    lossreg_kernel<<<1, 512>>>(rnum, envnum, out + 2 * GG * TASKS);

    // contrastive loss: S = hr @ henv^T
    transpose_kernel<<<(GG * EMB + 255) / 256, 256>>>(henv, henvT);
    dim3 gridS((GG + BN - 1) / BN, (GG + BM - 1) / BM);
    sgemm_opt<<<gridS, 256>>>(hr, henvT, nullptr, S, nullptr, GG, GG, EMB, 3);
    rowsum_kernel<<<GG, 256>>>(S, na, nc, rowsum);
    losscon_kernel<<<1, 512>>>(posdot, na, nb, rowsum, out + 2 * GG * TASKS + 1);

    // prediction MLPs
    hin_kernel<<<(GG * EMB + 255) / 256, 256>>>(hr, henv, perm, hin);
    dim3 gridP((EMB2 + BN - 1) / BN, (2 * GG + BM - 1) / BM);
    sgemm_opt<<<gridP, 256>>>(hin, Wp1, bp1, tmp, nullptr, 2 * GG, EMB2, EMB, 0);
    pred2_kernel<<<(2 * GG * TASKS + 127) / 128, 128>>>(tmp, Wp2, bp2, out);
}

// round 5
// speedup vs baseline: 1.7028x; 1.4163x over previous
#include <cuda_runtime.h>
#include <cuda_bf16.h>
#include <math.h>
#include <stdint.h>

#define NN 30000
#define EE 240000
#define GG 1500
#define EMB 300
#define EMB2 600
#define TASKS 12
#define GAMMA 0.4f
#define INV_T 5.0f   // 1 / T_CON

// ---------------- scratch (static device allocations only) ----------------
__device__ float d_xfeat[NN * EMB];
__device__ float d_hb[NN * EMB];
__device__ float d_xr[NN * EMB];
__device__ float d_agg[NN * EMB];
__device__ float d_tmp[NN * EMB2];
__device__ float d_gate[NN];
__device__ float d_hr[GG * EMB];
__device__ float d_henv[GG * EMB];
__device__ float d_hout[GG * EMB];
__device__ float d_henvT[EMB * GG];
__device__ float d_S[GG * GG];
__device__ float d_na[GG], d_nb[GG], d_nc[GG], d_posdot[GG];
__device__ float d_rnum[GG], d_envnum[GG];
__device__ float d_rowsum[GG];
__device__ float d_hin[2 * GG * EMB];

// ---------------- node encoder ----------------
__global__ void enc_kernel(const float* __restrict__ x, const float* __restrict__ W,
                           const float* __restrict__ b, float* __restrict__ out) {
    int idx = blockIdx.x * blockDim.x + threadIdx.x;
    if (idx >= NN * EMB) return;
    int i = idx / EMB, j = idx % EMB;
    const float* xr = x + i * 9;
    float acc = b[j];
#pragma unroll
    for (int k = 0; k < 9; k++) acc += xr[k] * W[k * EMB + j];
    out[idx] = acc;
}

// ------------- edge message passing: agg[dst] += relu(x[src] + ea@We + be) -------------
__global__ void edge_mp(const float* __restrict__ x, float* __restrict__ agg,
                        const int* __restrict__ src, const int* __restrict__ dst,
                        const float* __restrict__ ea, const float* __restrict__ We,
                        const float* __restrict__ be) {
    int w = (blockIdx.x * blockDim.x + threadIdx.x) >> 5;
    int lane = threadIdx.x & 31;
    if (w >= EE) return;
    int s = src[w], d = dst[w];
    float a0 = ea[w * 3 + 0], a1 = ea[w * 3 + 1], a2 = ea[w * 3 + 2];
    const float* xs = x + (size_t)s * EMB;
    float* ag = agg + (size_t)d * EMB;
    for (int k = lane; k < EMB; k += 32) {
        float e = fmaf(a0, We[k], fmaf(a1, We[EMB + k], fmaf(a2, We[2 * EMB + k], be[k])));
        float m = xs[k] + e;
        m = m > 0.f ? m : 0.f;
        atomicAdd(&ag[k], m);
    }
}

// ============================================================================
// bf16 3-term split GEMM on tensor cores (mma.m16n8k16, fp32 accum)
// C = A@B with A,B fp32; A=Ah+Al, B=Bh+Bl (bf16); C ≈ Ah Bh + Ah Bl + Al Bh
// CTA tile 128x128x32, 8 warps (2x4), warp tile 64x32.
// ep: 0 = +bias, relu ; 1 = +bias, relu, +resid ; 2 = +bias, +resid ; 3 = raw
// ============================================================================
#define TBM 128
#define TBN 128
#define TBK 32
#define A_STRIDE 40    // bf16 elems per row (32 + 8 pad) -> 80B, 16B-multiple
#define B_STRIDE 136   // u32 per row (128 + 8 pad)

#define A_BYTES (2 * 2 * TBM * A_STRIDE * 2)          // 40960
#define B_BYTES (2 * 2 * (TBK / 2) * B_STRIDE * 4)    // 69632
static const int BF16_SMEM = A_BYTES + B_BYTES;       // 110592

__device__ __forceinline__ uint32_t pack_bf2(__nv_bfloat16 lo, __nv_bfloat16 hi) {
    return ((uint32_t)__bfloat16_as_ushort(hi) << 16) | (uint32_t)__bfloat16_as_ushort(lo);
}

__global__ __launch_bounds__(256)
void bf16gemm3(const float* __restrict__ A, const float* __restrict__ B,
               const float* __restrict__ bias, float* __restrict__ C,
               const float* __restrict__ resid, int M, int N, int K, int ep) {
    extern __shared__ char smemraw[];
    __nv_bfloat16* Asm = (__nv_bfloat16*)smemraw;           // [2][2][128][A_STRIDE]
    uint32_t* Bsm = (uint32_t*)(smemraw + A_BYTES);         // [2][2][16][B_STRIDE]
#define ASI(buf, hl, r, k) Asm[(((buf) * 2 + (hl)) * TBM + (r)) * A_STRIDE + (k)]
#define BSI(buf, hl, k2, n) Bsm[(((buf) * 2 + (hl)) * (TBK / 2) + (k2)) * B_STRIDE + (n)]

    const int tid = threadIdx.x;
    const int wid = tid >> 5;
    const int lane = tid & 31;
    const int grp = lane >> 2;   // 0..7
    const int tig = lane & 3;    // 0..3
    const int wm = (wid >> 2) * 64;
    const int wn = (wid & 3) * 32;
    // ldmatrix lane->address map for 16x16 b16 tile (x4)
    const int lrow = ((lane >> 3) & 1) * 8 + (lane & 7);
    const int lcol = (lane >> 4) * 8;

    const int row0 = blockIdx.y * TBM;
    const int col0 = blockIdx.x * TBN;

    // A loader: rows tid>>3 (+32i), k cols (tid&7)*4
    const int arow = tid >> 3;
    const int acol = (tid & 7) * 4;
    // B loader: k-pair rows tid>>5 (+8i), n cols (tid&31)*4
    const int bk2 = tid >> 5;
    const int bnc = (tid & 31) * 4;

    float4 aR[4];
    float4 bR[2][2];   // [task][row-in-pair]

    auto loadRegs = [&](int kt) {
        int kb = kt * TBK;
#pragma unroll
        for (int i = 0; i < 4; i++) {
            int r = row0 + arow + 32 * i;
            int k = kb + acol;
            aR[i] = (r < M && k < K) ? *(const float4*)(A + (size_t)r * K + k)
                                     : make_float4(0.f, 0.f, 0.f, 0.f);
        }
#pragma unroll
        for (int i = 0; i < 2; i++) {
            int k2g = bk2 + 8 * i;
            int c = col0 + bnc;
            int k0g = kb + 2 * k2g;
#pragma unroll
            for (int rr = 0; rr < 2; rr++) {
                int k = k0g + rr;
                bR[i][rr] = (k < K && c < N) ? *(const float4*)(B + (size_t)k * N + c)
                                             : make_float4(0.f, 0.f, 0.f, 0.f);
            }
        }
    };
    auto storeRegs = [&](int buf) {
#pragma unroll
        for (int i = 0; i < 4; i++) {
            float v[4] = {aR[i].x, aR[i].y, aR[i].z, aR[i].w};
            __nv_bfloat16 h[4], l[4];
#pragma unroll
            for (int q = 0; q < 4; q++) {
                h[q] = __float2bfloat16(v[q]);
                l[q] = __float2bfloat16(v[q] - __bfloat162float(h[q]));
            }
            uint2 hp, lp;
            hp.x = pack_bf2(h[0], h[1]); hp.y = pack_bf2(h[2], h[3]);
            lp.x = pack_bf2(l[0], l[1]); lp.y = pack_bf2(l[2], l[3]);
            *(uint2*)&ASI(buf, 0, arow + 32 * i, acol) = hp;
            *(uint2*)&ASI(buf, 1, arow + 32 * i, acol) = lp;
        }
#pragma unroll
        for (int i = 0; i < 2; i++) {
            int k2 = bk2 + 8 * i;
            float r0[4] = {bR[i][0].x, bR[i][0].y, bR[i][0].z, bR[i][0].w};
            float r1[4] = {bR[i][1].x, bR[i][1].y, bR[i][1].z, bR[i][1].w};
            uint4 hp, lp;
            uint32_t* hpp = (uint32_t*)&hp;
            uint32_t* lpp = (uint32_t*)&lp;
#pragma unroll
            for (int n = 0; n < 4; n++) {
                __nv_bfloat16 h0 = __float2bfloat16(r0[n]);
                __nv_bfloat16 l0 = __float2bfloat16(r0[n] - __bfloat162float(h0));
                __nv_bfloat16 h1 = __float2bfloat16(r1[n]);
                __nv_bfloat16 l1 = __float2bfloat16(r1[n] - __bfloat162float(h1));
                hpp[n] = pack_bf2(h0, h1);   // low 16 = even k
                lpp[n] = pack_bf2(l0, l1);
            }
            *(uint4*)&BSI(buf, 0, k2, bnc) = hp;
            *(uint4*)&BSI(buf, 1, k2, bnc) = lp;
        }
    };

    float acc[4][4][4];
#pragma unroll
    for (int i = 0; i < 4; i++)
#pragma unroll
        for (int j = 0; j < 4; j++)
#pragma unroll
            for (int q = 0; q < 4; q++) acc[i][j][q] = 0.f;

    const int nk = (K + TBK - 1) / TBK;
    loadRegs(0);
    storeRegs(0);
    __syncthreads();

    for (int t = 0; t < nk; t++) {
        const int buf = t & 1;
        if (t + 1 < nk) loadRegs(t + 1);
#pragma unroll
        for (int ks = 0; ks < 2; ks++) {
            const int k0 = ks * 16;
            uint32_t ah[4][4], al[4][4], bh[4][2], bl[4][2];
#pragma unroll
            for (int mt = 0; mt < 4; mt++) {
                {
                    __nv_bfloat16* p = &ASI(buf, 0, wm + mt * 16 + lrow, k0 + lcol);
                    uint32_t sa = (uint32_t)__cvta_generic_to_shared(p);
                    asm volatile(
                        "ldmatrix.sync.aligned.m8n8.x4.shared.b16 {%0,%1,%2,%3}, [%4];"
                        : "=r"(ah[mt][0]), "=r"(ah[mt][1]), "=r"(ah[mt][2]), "=r"(ah[mt][3])
                        : "r"(sa));
                }
                {
                    __nv_bfloat16* p = &ASI(buf, 1, wm + mt * 16 + lrow, k0 + lcol);
                    uint32_t sa = (uint32_t)__cvta_generic_to_shared(p);
                    asm volatile(
                        "ldmatrix.sync.aligned.m8n8.x4.shared.b16 {%0,%1,%2,%3}, [%4];"
                        : "=r"(al[mt][0]), "=r"(al[mt][1]), "=r"(al[mt][2]), "=r"(al[mt][3])
                        : "r"(sa));
                }
            }
#pragma unroll
            for (int nt = 0; nt < 4; nt++) {
                int cc = wn + nt * 8 + grp;
                bh[nt][0] = BSI(buf, 0, ks * 8 + tig, cc);
                bh[nt][1] = BSI(buf, 0, ks * 8 + tig + 4, cc);
                bl[nt][0] = BSI(buf, 1, ks * 8 + tig, cc);
                bl[nt][1] = BSI(buf, 1, ks * 8 + tig + 4, cc);
            }
#pragma unroll
            for (int mt = 0; mt < 4; mt++)
#pragma unroll
                for (int nt = 0; nt < 4; nt++) {
#define MMA_BF16(AF, BF)                                                         \
    asm volatile(                                                                \
        "mma.sync.aligned.m16n8k16.row.col.f32.bf16.bf16.f32 "                   \
        "{%0,%1,%2,%3}, {%4,%5,%6,%7}, {%8,%9}, {%0,%1,%2,%3};"                  \
        : "+f"(acc[mt][nt][0]), "+f"(acc[mt][nt][1]),                            \
          "+f"(acc[mt][nt][2]), "+f"(acc[mt][nt][3])                             \
        : "r"(AF[mt][0]), "r"(AF[mt][1]), "r"(AF[mt][2]), "r"(AF[mt][3]),        \
          "r"(BF[nt][0]), "r"(BF[nt][1]))
                    MMA_BF16(ah, bh);
                    MMA_BF16(ah, bl);
                    MMA_BF16(al, bh);
#undef MMA_BF16
                }
        }
        if (t + 1 < nk) {
            storeRegs(buf ^ 1);
            __syncthreads();
        }
    }

    // epilogue
#pragma unroll
    for (int mt = 0; mt < 4; mt++) {
#pragma unroll
        for (int nt = 0; nt < 4; nt++) {
            int rA = row0 + wm + mt * 16 + grp;
            int cA = col0 + wn + nt * 8 + 2 * tig;
#pragma unroll
            for (int half = 0; half < 2; half++) {
                int r = rA + half * 8;
                if (r >= M) continue;
#pragma unroll
                for (int q = 0; q < 2; q++) {
                    int c = cA + q;
                    if (c >= N) continue;
                    float v = acc[mt][nt][half * 2 + q];
                    if (ep != 3) v += bias[c];
                    if (ep == 0 || ep == 1) v = fmaxf(v, 0.f);
                    if (ep == 1 || ep == 2) v += resid[(size_t)r * N + c];
                    C[(size_t)r * N + c] = v;
                }
            }
        }
    }
#undef ASI
#undef BSI
}

// ---------------- fp32 SGEMM (precision-critical small GEMMs) ----------------
#define BM 128
#define BN 128
#define BK 16
__global__ __launch_bounds__(256, 2)
void sgemm_opt(const float* __restrict__ A, const float* __restrict__ B,
               const float* __restrict__ bias, float* __restrict__ C,
               const float* __restrict__ resid, int M, int N, int K, int ep) {
    __shared__ float As[2][BK][BM + 4];
    __shared__ float Bs[2][BK][BN];

    const int tid = threadIdx.x;
    const int row0 = blockIdx.y * BM;
    const int col0 = blockIdx.x * BN;
    const int tx = tid & 15;
    const int ty = tid >> 4;

    const int ar = tid >> 1;
    const int ak0 = (tid & 1) * 8;
    const int br = tid >> 5;
    const int bc = (tid & 31) * 4;

    float4 aReg[2], bReg[2];

    const int gr = row0 + ar;
    const bool arow_ok = (gr < M);
    const float* Arow = A + (size_t)gr * K;

    auto loadA = [&](int k0) {
#pragma unroll
        for (int v = 0; v < 2; v++) {
            int k = k0 + ak0 + v * 4;
            float4 t = make_float4(0.f, 0.f, 0.f, 0.f);
            if (arow_ok) {
                if (k + 3 < K) {
                    t = *(const float4*)(Arow + k);
                } else {
                    float u[4] = {0.f, 0.f, 0.f, 0.f};
#pragma unroll
                    for (int q = 0; q < 4; q++) if (k + q < K) u[q] = Arow[k + q];
                    t = make_float4(u[0], u[1], u[2], u[3]);
                }
            }
            aReg[v] = t;
        }
    };
    auto loadB = [&](int k0) {
#pragma unroll
        for (int v = 0; v < 2; v++) {
            int k = k0 + br + v * 8;
            int c = col0 + bc;
            float4 t = make_float4(0.f, 0.f, 0.f, 0.f);
            if (k < K) {
                const float* Brow = B + (size_t)k * N;
                if (c + 3 < N) {
                    t = *(const float4*)(Brow + c);
                } else {
                    float u[4] = {0.f, 0.f, 0.f, 0.f};
#pragma unroll
                    for (int q = 0; q < 4; q++) if (c + q < N) u[q] = Brow[c + q];
                    t = make_float4(u[0], u[1], u[2], u[3]);
                }
            }
            bReg[v] = t;
        }
    };
    auto storeAB = [&](int buf) {
#pragma unroll
        for (int v = 0; v < 2; v++) {
            As[buf][ak0 + v * 4 + 0][ar] = aReg[v].x;
            As[buf][ak0 + v * 4 + 1][ar] = aReg[v].y;
            As[buf][ak0 + v * 4 + 2][ar] = aReg[v].z;
            As[buf][ak0 + v * 4 + 3][ar] = aReg[v].w;
            *(float4*)&Bs[buf][br + v * 8][bc] = bReg[v];
        }
    };

    float acc[8][8] = {};

    const int nk = (K + BK - 1) / BK;
    loadA(0); loadB(0);
    storeAB(0);
    __syncthreads();

    for (int t = 0; t < nk; t++) {
        const int buf = t & 1;
        if (t + 1 < nk) { loadA((t + 1) * BK); loadB((t + 1) * BK); }
#pragma unroll
        for (int kk = 0; kk < BK; kk++) {
            float a[8], b[8];
            *(float4*)&a[0] = *(const float4*)&As[buf][kk][ty * 8];
            *(float4*)&a[4] = *(const float4*)&As[buf][kk][ty * 8 + 4];
            *(float4*)&b[0] = *(const float4*)&Bs[buf][kk][tx * 8];
            *(float4*)&b[4] = *(const float4*)&Bs[buf][kk][tx * 8 + 4];
#pragma unroll
            for (int i = 0; i < 8; i++)
#pragma unroll
                for (int j = 0; j < 8; j++) acc[i][j] = fmaf(a[i], b[j], acc[i][j]);
        }
        if (t + 1 < nk) {
            storeAB(buf ^ 1);
            __syncthreads();
        }
    }

#pragma unroll
    for (int i = 0; i < 8; i++) {
        int r = row0 + ty * 8 + i;
        if (r >= M) continue;
#pragma unroll
        for (int j = 0; j < 8; j++) {
            int c = col0 + tx * 8 + j;
            if (c >= N) continue;
            float v = acc[i][j];
            if (ep != 3) v += bias[c];
            if (ep == 0 || ep == 1) v = fmaxf(v, 0.f);
            if (ep == 1 || ep == 2) v += resid[(size_t)r * N + c];
            C[(size_t)r * N + c] = v;
        }
    }
}

// ---------------- gate ----------------
__global__ void gate_kernel(const float* __restrict__ tmp, const float* __restrict__ Wg2,
                            const float* __restrict__ bg2, const float* __restrict__ gumbel,
                            float* __restrict__ gate) {
    int w = (blockIdx.x * blockDim.x + threadIdx.x) >> 5;
    int lane = threadIdx.x & 31;
    if (w >= NN) return;
    const float* row = tmp + (size_t)w * EMB2;
    float a0 = 0.f, a1 = 0.f;
    for (int k = lane; k < EMB2; k += 32) {
        float v = row[k];
        a0 = fmaf(v, Wg2[2 * k + 0], a0);
        a1 = fmaf(v, Wg2[2 * k + 1], a1);
    }
    for (int o = 16; o; o >>= 1) {
        a0 += __shfl_down_sync(0xffffffffu, a0, o);
        a1 += __shfl_down_sync(0xffffffffu, a1, o);
    }
    if (lane == 0) {
        float z0 = a0 + bg2[0] + gumbel[2 * w + 0];
        float z1 = a1 + bg2[1] + gumbel[2 * w + 1];
        gate[w] = 1.f / (1.f + expf(z0 - z1));
    }
}

// ---------------- per-graph segment means (batch is sorted) ----------------
__device__ __forceinline__ int lower_bound_batch(const int* __restrict__ batch, int val) {
    int lo = 0, hi = NN;
    while (lo < hi) {
        int mid = (lo + hi) >> 1;
        if (batch[mid] < val) lo = mid + 1; else hi = mid;
    }
    return lo;
}

__global__ void segment_kernel(const float* __restrict__ hb, const float* __restrict__ gate,
                               const int* __restrict__ batch,
                               float* __restrict__ hr, float* __restrict__ henv,
                               float* __restrict__ hout, float* __restrict__ rnum,
                               float* __restrict__ envnum) {
    int g = blockIdx.x;
    int s = lower_bound_batch(batch, g);
    int e = lower_bound_batch(batch, g + 1);
    float cnt = fmaxf((float)(e - s), 1.f);
    int tid = threadIdx.x;
    if (tid < EMB) {
        float ar = 0.f, ae = 0.f, ao = 0.f;
        for (int n = s; n < e; n++) {
            float h = hb[(size_t)n * EMB + tid];
            float gt = gate[n];
            ar = fmaf(gt, h, ar);
            ae = fmaf(1.f - gt, h, ae);
            ao += h;
        }
        hr[g * EMB + tid] = ar / cnt;
        henv[g * EMB + tid] = ae / cnt;
        hout[g * EMB + tid] = ao / cnt;
    }
    __shared__ float sh[512];
    float gs = 0.f;
    for (int n = s + tid; n < e; n += blockDim.x) gs += gate[n];
    sh[tid] = gs;
    __syncthreads();
    for (int o = 256; o; o >>= 1) {
        if (tid < o) sh[tid] += sh[tid + o];
        __syncthreads();
    }
    if (tid == 0) {
        rnum[g] = sh[0] + 1e-8f;
        envnum[g] = ((float)(e - s) - sh[0]) + 1e-8f;
    }
}

// ---------------- per-graph norms + diagonal dot ----------------
__global__ void norm_kernel(const float* __restrict__ hr, const float* __restrict__ henv,
                            const float* __restrict__ hout, float* __restrict__ na,
                            float* __restrict__ nb, float* __restrict__ nc,
                            float* __restrict__ posdot) {
    int g = blockIdx.x, tid = threadIdx.x;
    float s1 = 0, s2 = 0, s3 = 0, s4 = 0;
    for (int d = tid; d < EMB; d += 128) {
        float a = hr[g * EMB + d], o = hout[g * EMB + d], ev = henv[g * EMB + d];
        s1 = fmaf(a, a, s1); s2 = fmaf(o, o, s2); s3 = fmaf(ev, ev, s3); s4 = fmaf(a, o, s4);
    }
    __shared__ float sh[128];
    auto red = [&](float v) -> float {
        sh[tid] = v; __syncthreads();
        for (int o = 64; o; o >>= 1) { if (tid < o) sh[tid] += sh[tid + o]; __syncthreads(); }
        float r = sh[0]; __syncthreads();
        return r;
    };
    float r1 = red(s1), r2 = red(s2), r3 = red(s3), r4 = red(s4);
    if (tid == 0) {
        na[g] = sqrtf(r1); nb[g] = sqrtf(r2); nc[g] = sqrtf(r3); posdot[g] = r4;
    }
}

__global__ void lossreg_kernel(const float* __restrict__ rnum, const float* __restrict__ envnum,
                               float* __restrict__ out) {
    int tid = threadIdx.x;
    float local = 0.f;
    for (int g = tid; g < GG; g += 512) {
        float r = rnum[g], ev = envnum[g];
        local += fabsf(r / (r + ev) - GAMMA);
    }
    __shared__ float sh[512];
    sh[tid] = local; __syncthreads();
    for (int o = 256; o; o >>= 1) { if (tid < o) sh[tid] += sh[tid + o]; __syncthreads(); }
    if (tid == 0) out[0] = sh[0] / (float)GG;
}

__global__ void transpose_kernel(const float* __restrict__ henv, float* __restrict__ henvT) {
    int idx = blockIdx.x * blockDim.x + threadIdx.x;
    if (idx >= GG * EMB) return;
    int g = idx / EMB, d = idx % EMB;
    henvT[d * GG + g] = henv[idx];
}

__global__ void rowsum_kernel(const float* __restrict__ S, const float* __restrict__ na,
                              const float* __restrict__ nc, float* __restrict__ rowsum) {
    int g = blockIdx.x, tid = threadIdx.x;
    float nag = na[g];
    float local = 0.f;
    for (int j = tid; j < GG; j += 256) {
        float denom = nag * nc[j] + 1e-8f;
        local += expf(S[(size_t)g * GG + j] / denom * INV_T);
    }
    __shared__ float sh[256];
    sh[tid] = local; __syncthreads();
    for (int o = 128; o; o >>= 1) { if (tid < o) sh[tid] += sh[tid + o]; __syncthreads(); }
    if (tid == 0) rowsum[g] = sh[0];
}

__global__ void losscon_kernel(const float* __restrict__ posdot, const float* __restrict__ na,
                               const float* __restrict__ nb, const float* __restrict__ rowsum,
                               float* __restrict__ out) {
    int tid = threadIdx.x;
    float local = 0.f;
    for (int g = tid; g < GG; g += 512) {
        float pos = expf(posdot[g] / (na[g] * nb[g] + 1e-8f) * INV_T);
        local += -logf(pos / (rowsum[g] + pos));
    }
    __shared__ float sh[512];
    sh[tid] = local; __syncthreads();
    for (int o = 256; o; o >>= 1) { if (tid < o) sh[tid] += sh[tid + o]; __syncthreads(); }
    if (tid == 0) out[0] = sh[0] / (float)GG;
}

__global__ void hin_kernel(const float* __restrict__ hr, const float* __restrict__ henv,
                           const int* __restrict__ perm, float* __restrict__ hin) {
    int idx = blockIdx.x * blockDim.x + threadIdx.x;
    if (idx >= GG * EMB) return;
    int g = idx / EMB, d = idx % EMB;
    float r = hr[idx];
    hin[idx] = r + henv[(size_t)perm[g] * EMB + d];
    hin[(size_t)(GG + g) * EMB + d] = r;
}

__global__ void pred2_kernel(const float* __restrict__ tmp, const float* __restrict__ Wp2,
                             const float* __restrict__ bp2, float* __restrict__ out) {
    int idx = blockIdx.x * blockDim.x + threadIdx.x;
    if (idx >= 2 * GG * TASKS) return;
    int row = idx / TASKS, t = idx % TASKS;
    const float* r = tmp + (size_t)row * EMB2;
    float acc = bp2[t];
    for (int k = 0; k < EMB2; k++) acc = fmaf(r[k], Wp2[k * TASKS + t], acc);
    int o = (row < GG) ? (row * TASKS + t) : (GG * TASKS + (row - GG) * TASKS + t);
    out[o] = acc;
}

// =====================================================================================
extern "C" void kernel_launch(void* const* d_in, const int* in_sizes, int n_in,
                              void* d_out, int out_size) {
    const float* x         = (const float*)d_in[0];
    const float* edge_attr = (const float*)d_in[1];
    const int*   edge_index= (const int*)  d_in[2];
    const int*   batch     = (const int*)  d_in[3];
    const float* gumbel    = (const float*)d_in[4];
    const int*   perm      = (const int*)  d_in[5];
    const float* W_enc = (const float*)d_in[6];
    const float* b_enc = (const float*)d_in[7];
    const float* We_g  = (const float*)d_in[8];
    const float* be_g  = (const float*)d_in[9];
    const float* W1_g  = (const float*)d_in[10];
    const float* b1_g  = (const float*)d_in[11];
    const float* W2_g  = (const float*)d_in[12];
    const float* b2_g  = (const float*)d_in[13];
    const float* We_r  = (const float*)d_in[14];
    const float* be_r  = (const float*)d_in[15];
    const float* W1_r  = (const float*)d_in[16];
    const float* b1_r  = (const float*)d_in[17];
    const float* W2_r  = (const float*)d_in[18];
    const float* b2_r  = (const float*)d_in[19];
    const float* Wg1   = (const float*)d_in[20];
    const float* bg1   = (const float*)d_in[21];
    const float* Wg2   = (const float*)d_in[22];
    const float* bg2   = (const float*)d_in[23];
    const float* Wp1   = (const float*)d_in[24];
    const float* bp1   = (const float*)d_in[25];
    const float* Wp2   = (const float*)d_in[26];
    const float* bp2   = (const float*)d_in[27];
    float* out = (float*)d_out;

    const int* src = edge_index;
    const int* dst = edge_index + EE;

    float *xfeat, *hb, *xr, *agg, *tmp, *gate, *hr, *henv, *hout, *henvT, *S;
    float *na, *nb, *nc, *posdot, *rnum, *envnum, *rowsum, *hin;
    cudaGetSymbolAddress((void**)&xfeat, d_xfeat);
    cudaGetSymbolAddress((void**)&hb, d_hb);
    cudaGetSymbolAddress((void**)&xr, d_xr);
    cudaGetSymbolAddress((void**)&agg, d_agg);
    cudaGetSymbolAddress((void**)&tmp, d_tmp);
    cudaGetSymbolAddress((void**)&gate, d_gate);
    cudaGetSymbolAddress((void**)&hr, d_hr);
    cudaGetSymbolAddress((void**)&henv, d_henv);
    cudaGetSymbolAddress((void**)&hout, d_hout);
    cudaGetSymbolAddress((void**)&henvT, d_henvT);
    cudaGetSymbolAddress((void**)&S, d_S);
    cudaGetSymbolAddress((void**)&na, d_na);
    cudaGetSymbolAddress((void**)&nb, d_nb);
    cudaGetSymbolAddress((void**)&nc, d_nc);
    cudaGetSymbolAddress((void**)&posdot, d_posdot);
    cudaGetSymbolAddress((void**)&rnum, d_rnum);
    cudaGetSymbolAddress((void**)&envnum, d_envnum);
    cudaGetSymbolAddress((void**)&rowsum, d_rowsum);
    cudaGetSymbolAddress((void**)&hin, d_hin);

    cudaFuncSetAttribute(bf16gemm3, cudaFuncAttributeMaxDynamicSharedMemorySize, BF16_SMEM);

    const size_t rowBytes = (size_t)NN * EMB * sizeof(float);

    enc_kernel<<<(NN * EMB + 255) / 256, 256>>>(x, W_enc, b_enc, xfeat);
    cudaMemcpyAsync(hb, xfeat, rowBytes, cudaMemcpyDeviceToDevice);
    cudaMemcpyAsync(xr, xfeat, rowBytes, cudaMemcpyDeviceToDevice);

    dim3 gridT1((EMB2 + TBN - 1) / TBN, (NN + TBM - 1) / TBM);   // N=600
    dim3 gridT2((EMB + TBN - 1) / TBN, (NN + TBM - 1) / TBM);    // N=300
    const int edgeBlocks = (EE + 7) / 8;

    // enc GIN stack (L=5)
    for (int l = 0; l < 5; l++) {
        cudaMemcpyAsync(agg, hb, rowBytes, cudaMemcpyDeviceToDevice);
        edge_mp<<<edgeBlocks, 256>>>(hb, agg, src, dst, edge_attr,
                                     We_g + l * 3 * EMB, be_g + l * EMB);
        bf16gemm3<<<gridT1, 256, BF16_SMEM>>>(agg, W1_g + (size_t)l * EMB * EMB2, b1_g + l * EMB2,
                                              tmp, nullptr, NN, EMB2, EMB, 0);
        bf16gemm3<<<gridT2, 256, BF16_SMEM>>>(tmp, W2_g + (size_t)l * EMB2 * EMB, b2_g + l * EMB,
                                              hb, hb, NN, EMB, EMB2, (l < 4) ? 1 : 2);
    }
    // rat GIN stack (L=2)
    for (int l = 0; l < 2; l++) {
        cudaMemcpyAsync(agg, xr, rowBytes, cudaMemcpyDeviceToDevice);
        edge_mp<<<edgeBlocks, 256>>>(xr, agg, src, dst, edge_attr,
                                     We_r + l * 3 * EMB, be_r + l * EMB);
        bf16gemm3<<<gridT1, 256, BF16_SMEM>>>(agg, W1_r + (size_t)l * EMB * EMB2, b1_r + l * EMB2,
                                              tmp, nullptr, NN, EMB2, EMB, 0);
        bf16gemm3<<<gridT2, 256, BF16_SMEM>>>(tmp, W2_r + (size_t)l * EMB2 * EMB, b2_r + l * EMB,
                                              xr, xr, NN, EMB, EMB2, (l < 1) ? 1 : 2);
    }

    // gate
    bf16gemm3<<<gridT1, 256, BF16_SMEM>>>(xr, Wg1, bg1, tmp, nullptr, NN, EMB2, EMB, 0);
    gate_kernel<<<(NN * 32 + 255) / 256, 256>>>(tmp, Wg2, bg2, gumbel, gate);

    // per-graph reductions
    segment_kernel<<<GG, 512>>>(hb, gate, batch, hr, henv, hout, rnum, envnum);
    norm_kernel<<<GG, 128>>>(hr, henv, hout, na, nb, nc, posdot);
    lossreg_kernel<<<1, 512>>>(rnum, envnum, out + 2 * GG * TASKS);

    // contrastive loss: S = hr @ henv^T (fp32: feeds exp(5*cos))
    transpose_kernel<<<(GG * EMB + 255) / 256, 256>>>(henv, henvT);
    dim3 gridS((GG + BN - 1) / BN, (GG + BM - 1) / BM);
    sgemm_opt<<<gridS, 256>>>(hr, henvT, nullptr, S, nullptr, GG, GG, EMB, 3);
    rowsum_kernel<<<GG, 256>>>(S, na, nc, rowsum);
    losscon_kernel<<<1, 512>>>(posdot, na, nb, rowsum, out + 2 * GG * TASKS + 1);

    // prediction MLPs
    hin_kernel<<<(GG * EMB + 255) / 256, 256>>>(hr, henv, perm, hin);
    dim3 gridP((EMB2 + BN - 1) / BN, (2 * GG + BM - 1) / BM);
    sgemm_opt<<<gridP, 256>>>(hin, Wp1, bp1, tmp, nullptr, 2 * GG, EMB2, EMB, 0);
    pred2_kernel<<<(2 * GG * TASKS + 127) / 128, 128>>>(tmp, Wp2, bp2, out);
}

// round 6
// speedup vs baseline: 1.7404x; 1.0221x over previous
#include <cuda_runtime.h>
#include <cuda_bf16.h>
#include <math.h>
#include <stdint.h>

#define NN 30000
#define EE 240000
#define GG 1500
#define EMB 300
#define EMB2 600
#define TASKS 12
#define GAMMA 0.4f
#define INV_T 5.0f   // 1 / T_CON

#define KP3 904      // padded 3*300
#define KP6 1800     // 3*600 (already mult of 8)

// ---------------- scratch (static device allocations only) ----------------
__device__ float d_xfeat[NN * EMB];
__device__ float d_hb[NN * EMB];
__device__ float d_xr[NN * EMB];
__device__ float d_agg[NN * EMB];
__device__ float d_tmp[NN * EMB2];
__device__ float d_gate[NN];
__device__ float d_hr[GG * EMB];
__device__ float d_henv[GG * EMB];
__device__ float d_hout[GG * EMB];
__device__ float d_henvT[EMB * GG];
__device__ float d_S[GG * GG];
__device__ float d_na[GG], d_nb[GG], d_nc[GG], d_posdot[GG];
__device__ float d_rnum[GG], d_envnum[GG];
__device__ float d_rowsum[GG];
__device__ float d_hin[2 * GG * EMB];
// stacked bf16 operands
__device__ __nv_bfloat16 d_AS[(size_t)NN * KP3];     // split of [M,300] activations
__device__ __nv_bfloat16 d_tmpS[(size_t)NN * KP6];   // split of GEMM1 output [M,600]
__device__ __nv_bfloat16 d_WS1[900 * 600];           // split of [300,600] weights
__device__ __nv_bfloat16 d_WS2[1800 * 304];          // split of [600,300] weights

// ---------------- node encoder ----------------
__global__ void enc_kernel(const float* __restrict__ x, const float* __restrict__ W,
                           const float* __restrict__ b, float* __restrict__ out) {
    int idx = blockIdx.x * blockDim.x + threadIdx.x;
    if (idx >= NN * EMB) return;
    int i = idx / EMB, j = idx % EMB;
    const float* xr = x + i * 9;
    float acc = b[j];
#pragma unroll
    for (int k = 0; k < 9; k++) acc += xr[k] * W[k * EMB + j];
    out[idx] = acc;
}

// ------------- edge message passing: agg[dst] += relu(x[src] + ea@We + be) -------------
__global__ void edge_mp(const float* __restrict__ x, float* __restrict__ agg,
                        const int* __restrict__ src, const int* __restrict__ dst,
                        const float* __restrict__ ea, const float* __restrict__ We,
                        const float* __restrict__ be) {
    int w = (blockIdx.x * blockDim.x + threadIdx.x) >> 5;
    int lane = threadIdx.x & 31;
    if (w >= EE) return;
    int s = src[w], d = dst[w];
    float a0 = ea[w * 3 + 0], a1 = ea[w * 3 + 1], a2 = ea[w * 3 + 2];
    const float* xs = x + (size_t)s * EMB;
    float* ag = agg + (size_t)d * EMB;
    for (int k = lane; k < EMB; k += 32) {
        float e = fmaf(a0, We[k], fmaf(a1, We[EMB + k], fmaf(a2, We[2 * EMB + k], be[k])));
        float m = xs[k] + e;
        m = m > 0.f ? m : 0.f;
        atomicAdd(&ag[k], m);
    }
}

// ---------------- splits: x = hi + lo (bf16 pair) ----------------
// A' row layout (K=300): [hi(0..299) | lo(300..599) | hi(600..899) | 0 pad(900..903)]
__global__ void splitA_kernel(const float* __restrict__ in, int M,
                              __nv_bfloat16* __restrict__ out) {
    int idx = blockIdx.x * blockDim.x + threadIdx.x;
    if (idx >= M * 304) return;
    int m = idx / 304, q = idx % 304;
    __nv_bfloat16* row = out + (size_t)m * KP3;
    if (q < 300) {
        float v = in[(size_t)m * 300 + q];
        __nv_bfloat16 h = __float2bfloat16(v);
        __nv_bfloat16 l = __float2bfloat16(v - __bfloat162float(h));
        row[q] = h; row[300 + q] = l; row[600 + q] = h;
    } else {
        row[600 + q] = __float2bfloat16(0.f);   // 900..903 pad
    }
}

// B' rows (K logical): [hi rows 0..K-1 | hi rows K..2K-1 | lo rows 2K..3K-1], cols padded Np
__global__ void splitW_kernel(const float* __restrict__ W, int K, int N, int Np,
                              __nv_bfloat16* __restrict__ WS) {
    int idx = blockIdx.x * blockDim.x + threadIdx.x;
    if (idx >= K * Np) return;
    int k = idx / Np, n = idx % Np;
    __nv_bfloat16 h, l;
    if (n < N) {
        float v = W[(size_t)k * N + n];
        h = __float2bfloat16(v);
        l = __float2bfloat16(v - __bfloat162float(h));
    } else {
        h = __float2bfloat16(0.f); l = h;
    }
    WS[(size_t)k * Np + n] = h;
    WS[(size_t)(K + k) * Np + n] = h;
    WS[(size_t)(2 * K + k) * Np + n] = l;
}

// ============================================================================
// bf16 HMMA GEMM on pre-stacked operands. C = A'[M,K3] @ B'[K3,N]
// 128x128x32 tile, 8 warps (2x4), warp 64x32, cp.async double buffer.
// ep: 0 = +bias,relu -> C fp32 ; 1 = +bias,relu,+resid ; 2 = +bias,+resid ;
//     4 = +bias,relu -> outS split-bf16 [h|l|h] rows of ldS
// ============================================================================
#define HBM 128
#define HBN 128
#define HBK 32
#define HA_STR 40
#define HB_STR 136

__global__ __launch_bounds__(256, 2)
void hgemm(const __nv_bfloat16* __restrict__ A, int lda,
           const __nv_bfloat16* __restrict__ B, int ldb,
           const float* __restrict__ bias, float* __restrict__ C,
           const float* __restrict__ resid,
           __nv_bfloat16* __restrict__ outS, int ldS,
           int M, int N, int K3, int ep) {
    __shared__ __nv_bfloat16 Asm[2][HBM][HA_STR];
    __shared__ __nv_bfloat16 Bsm[2][HBK][HB_STR];

    const int tid = threadIdx.x;
    const int wid = tid >> 5, lane = tid & 31;
    const int grp = lane >> 2, tig = lane & 3;
    const int wm = (wid >> 2) * 64, wn = (wid & 3) * 32;
    const int lrow = lane & 15, lcol = (lane >> 4) * 8;

    const int row0 = blockIdx.y * HBM;
    const int col0 = blockIdx.x * HBN;

    auto loadTile = [&](int t, int buf) {
        int kb = t * HBK;
#pragma unroll
        for (int i = 0; i < 2; i++) {
            int c = tid * 2 + i;
            int ar = c >> 2, ak = (c & 3) * 8;
            const __nv_bfloat16* gp = A + (size_t)(row0 + ar) * lda + kb + ak;
            uint32_t sp = (uint32_t)__cvta_generic_to_shared(&Asm[buf][ar][ak]);
            int sz = ((row0 + ar) < M && (kb + ak) < lda) ? 16 : 0;
            asm volatile("cp.async.cg.shared.global [%0], [%1], 16, %2;"
                         :: "r"(sp), "l"(gp), "r"(sz) : "memory");
        }
#pragma unroll
        for (int i = 0; i < 2; i++) {
            int c = tid * 2 + i;
            int br = c >> 4, bn = (c & 15) * 8;
            const __nv_bfloat16* gp = B + (size_t)(kb + br) * ldb + col0 + bn;
            uint32_t sp = (uint32_t)__cvta_generic_to_shared(&Bsm[buf][br][bn]);
            int sz = ((kb + br) < K3 && (col0 + bn) < ldb) ? 16 : 0;
            asm volatile("cp.async.cg.shared.global [%0], [%1], 16, %2;"
                         :: "r"(sp), "l"(gp), "r"(sz) : "memory");
        }
        asm volatile("cp.async.commit_group;" ::: "memory");
    };

    float acc[4][4][4];
#pragma unroll
    for (int i = 0; i < 4; i++)
#pragma unroll
        for (int j = 0; j < 4; j++)
#pragma unroll
            for (int q = 0; q < 4; q++) acc[i][j][q] = 0.f;

    const int nk = (K3 + HBK - 1) / HBK;
    loadTile(0, 0);

    for (int t = 0; t < nk; t++) {
        const int buf = t & 1;
        if (t + 1 < nk) {
            loadTile(t + 1, buf ^ 1);
            asm volatile("cp.async.wait_group 1;" ::: "memory");
        } else {
            asm volatile("cp.async.wait_group 0;" ::: "memory");
        }
        __syncthreads();
#pragma unroll
        for (int ks = 0; ks < 2; ks++) {
            const int k0 = ks * 16;
            uint32_t af[4][4], bf[4][2];
#pragma unroll
            for (int mt = 0; mt < 4; mt++) {
                uint32_t sa = (uint32_t)__cvta_generic_to_shared(
                    &Asm[buf][wm + mt * 16 + lrow][k0 + lcol]);
                asm volatile(
                    "ldmatrix.sync.aligned.m8n8.x4.shared.b16 {%0,%1,%2,%3}, [%4];"
                    : "=r"(af[mt][0]), "=r"(af[mt][1]), "=r"(af[mt][2]), "=r"(af[mt][3])
                    : "r"(sa));
            }
#pragma unroll
            for (int ng = 0; ng < 2; ng++) {
                uint32_t sb = (uint32_t)__cvta_generic_to_shared(
                    &Bsm[buf][k0 + lrow][wn + ng * 16 + lcol]);
                uint32_t r0, r1, r2, r3;
                asm volatile(
                    "ldmatrix.sync.aligned.m8n8.x4.trans.shared.b16 {%0,%1,%2,%3}, [%4];"
                    : "=r"(r0), "=r"(r1), "=r"(r2), "=r"(r3) : "r"(sb));
                bf[ng * 2][0] = r0; bf[ng * 2][1] = r1;
                bf[ng * 2 + 1][0] = r2; bf[ng * 2 + 1][1] = r3;
            }
#pragma unroll
            for (int mt = 0; mt < 4; mt++)
#pragma unroll
                for (int nt = 0; nt < 4; nt++)
                    asm volatile(
                        "mma.sync.aligned.m16n8k16.row.col.f32.bf16.bf16.f32 "
                        "{%0,%1,%2,%3}, {%4,%5,%6,%7}, {%8,%9}, {%0,%1,%2,%3};"
                        : "+f"(acc[mt][nt][0]), "+f"(acc[mt][nt][1]),
                          "+f"(acc[mt][nt][2]), "+f"(acc[mt][nt][3])
                        : "r"(af[mt][0]), "r"(af[mt][1]), "r"(af[mt][2]), "r"(af[mt][3]),
                          "r"(bf[nt][0]), "r"(bf[nt][1]));
        }
        __syncthreads();
    }

    // epilogue
#pragma unroll
    for (int mt = 0; mt < 4; mt++) {
#pragma unroll
        for (int nt = 0; nt < 4; nt++) {
            int rA = row0 + wm + mt * 16 + grp;
            int cA = col0 + wn + nt * 8 + 2 * tig;
#pragma unroll
            for (int half = 0; half < 2; half++) {
                int r = rA + half * 8;
                if (r >= M) continue;
#pragma unroll
                for (int q = 0; q < 2; q++) {
                    int c = cA + q;
                    if (c >= N) continue;
                    float v = acc[mt][nt][half * 2 + q] + bias[c];
                    if (ep != 2) v = fmaxf(v, 0.f);
                    if (ep == 4) {
                        __nv_bfloat16 h = __float2bfloat16(v);
                        __nv_bfloat16 l = __float2bfloat16(v - __bfloat162float(h));
                        __nv_bfloat16* rowS = outS + (size_t)r * ldS;
                        rowS[c] = h; rowS[N + c] = l; rowS[2 * N + c] = h;
                    } else {
                        if (ep == 1 || ep == 2) v += resid[(size_t)r * N + c];
                        C[(size_t)r * N + c] = v;
                    }
                }
            }
        }
    }
}

// ---------------- fp32 SGEMM (S matrix only) ----------------
#define BM 128
#define BN 128
#define BK 16
__global__ __launch_bounds__(256, 2)
void sgemm_opt(const float* __restrict__ A, const float* __restrict__ B,
               const float* __restrict__ bias, float* __restrict__ C,
               const float* __restrict__ resid, int M, int N, int K, int ep) {
    __shared__ float As[2][BK][BM + 4];
    __shared__ float Bs[2][BK][BN];

    const int tid = threadIdx.x;
    const int row0 = blockIdx.y * BM;
    const int col0 = blockIdx.x * BN;
    const int tx = tid & 15;
    const int ty = tid >> 4;

    const int ar = tid >> 1;
    const int ak0 = (tid & 1) * 8;
    const int br = tid >> 5;
    const int bc = (tid & 31) * 4;

    float4 aReg[2], bReg[2];

    const int gr = row0 + ar;
    const bool arow_ok = (gr < M);
    const float* Arow = A + (size_t)gr * K;

    auto loadA = [&](int k0) {
#pragma unroll
        for (int v = 0; v < 2; v++) {
            int k = k0 + ak0 + v * 4;
            float4 t = make_float4(0.f, 0.f, 0.f, 0.f);
            if (arow_ok) {
                if (k + 3 < K) {
                    t = *(const float4*)(Arow + k);
                } else {
                    float u[4] = {0.f, 0.f, 0.f, 0.f};
#pragma unroll
                    for (int q = 0; q < 4; q++) if (k + q < K) u[q] = Arow[k + q];
                    t = make_float4(u[0], u[1], u[2], u[3]);
                }
            }
            aReg[v] = t;
        }
    };
    auto loadB = [&](int k0) {
#pragma unroll
        for (int v = 0; v < 2; v++) {
            int k = k0 + br + v * 8;
            int c = col0 + bc;
            float4 t = make_float4(0.f, 0.f, 0.f, 0.f);
            if (k < K) {
                const float* Brow = B + (size_t)k * N;
                if (c + 3 < N) {
                    t = *(const float4*)(Brow + c);
                } else {
                    float u[4] = {0.f, 0.f, 0.f, 0.f};
#pragma unroll
                    for (int q = 0; q < 4; q++) if (c + q < N) u[q] = Brow[c + q];
                    t = make_float4(u[0], u[1], u[2], u[3]);
                }
            }
            bReg[v] = t;
        }
    };
    auto storeAB = [&](int buf) {
#pragma unroll
        for (int v = 0; v < 2; v++) {
            As[buf][ak0 + v * 4 + 0][ar] = aReg[v].x;
            As[buf][ak0 + v * 4 + 1][ar] = aReg[v].y;
            As[buf][ak0 + v * 4 + 2][ar] = aReg[v].z;
            As[buf][ak0 + v * 4 + 3][ar] = aReg[v].w;
            *(float4*)&Bs[buf][br + v * 8][bc] = bReg[v];
        }
    };

    float acc[8][8] = {};

    const int nk = (K + BK - 1) / BK;
    loadA(0); loadB(0);
    storeAB(0);
    __syncthreads();

    for (int t = 0; t < nk; t++) {
        const int buf = t & 1;
        if (t + 1 < nk) { loadA((t + 1) * BK); loadB((t + 1) * BK); }
#pragma unroll
        for (int kk = 0; kk < BK; kk++) {
            float a[8], b[8];
            *(float4*)&a[0] = *(const float4*)&As[buf][kk][ty * 8];
            *(float4*)&a[4] = *(const float4*)&As[buf][kk][ty * 8 + 4];
            *(float4*)&b[0] = *(const float4*)&Bs[buf][kk][tx * 8];
            *(float4*)&b[4] = *(const float4*)&Bs[buf][kk][tx * 8 + 4];
#pragma unroll
            for (int i = 0; i < 8; i++)
#pragma unroll
                for (int j = 0; j < 8; j++) acc[i][j] = fmaf(a[i], b[j], acc[i][j]);
        }
        if (t + 1 < nk) {
            storeAB(buf ^ 1);
            __syncthreads();
        }
    }

#pragma unroll
    for (int i = 0; i < 8; i++) {
        int r = row0 + ty * 8 + i;
        if (r >= M) continue;
#pragma unroll
        for (int j = 0; j < 8; j++) {
            int c = col0 + tx * 8 + j;
            if (c >= N) continue;
            float v = acc[i][j];
            if (ep != 3) v += bias[c];
            if (ep == 0 || ep == 1) v = fmaxf(v, 0.f);
            if (ep == 1 || ep == 2) v += resid[(size_t)r * N + c];
            C[(size_t)r * N + c] = v;
        }
    }
}

// ---------------- gate ----------------
__global__ void gate_kernel(const float* __restrict__ tmp, const float* __restrict__ Wg2,
                            const float* __restrict__ bg2, const float* __restrict__ gumbel,
                            float* __restrict__ gate) {
    int w = (blockIdx.x * blockDim.x + threadIdx.x) >> 5;
    int lane = threadIdx.x & 31;
    if (w >= NN) return;
    const float* row = tmp + (size_t)w * EMB2;
    float a0 = 0.f, a1 = 0.f;
    for (int k = lane; k < EMB2; k += 32) {
        float v = row[k];
        a0 = fmaf(v, Wg2[2 * k + 0], a0);
        a1 = fmaf(v, Wg2[2 * k + 1], a1);
    }
    for (int o = 16; o; o >>= 1) {
        a0 += __shfl_down_sync(0xffffffffu, a0, o);
        a1 += __shfl_down_sync(0xffffffffu, a1, o);
    }
    if (lane == 0) {
        float z0 = a0 + bg2[0] + gumbel[2 * w + 0];
        float z1 = a1 + bg2[1] + gumbel[2 * w + 1];
        gate[w] = 1.f / (1.f + expf(z0 - z1));
    }
}

// ---------------- per-graph segment means (batch is sorted) ----------------
__device__ __forceinline__ int lower_bound_batch(const int* __restrict__ batch, int val) {
    int lo = 0, hi = NN;
    while (lo < hi) {
        int mid = (lo + hi) >> 1;
        if (batch[mid] < val) lo = mid + 1; else hi = mid;
    }
    return lo;
}

__global__ void segment_kernel(const float* __restrict__ hb, const float* __restrict__ gate,
                               const int* __restrict__ batch,
                               float* __restrict__ hr, float* __restrict__ henv,
                               float* __restrict__ hout, float* __restrict__ rnum,
                               float* __restrict__ envnum) {
    int g = blockIdx.x;
    int s = lower_bound_batch(batch, g);
    int e = lower_bound_batch(batch, g + 1);
    float cnt = fmaxf((float)(e - s), 1.f);
    int tid = threadIdx.x;
    if (tid < EMB) {
        float ar = 0.f, ae = 0.f, ao = 0.f;
        for (int n = s; n < e; n++) {
            float h = hb[(size_t)n * EMB + tid];
            float gt = gate[n];
            ar = fmaf(gt, h, ar);
            ae = fmaf(1.f - gt, h, ae);
            ao += h;
        }
        hr[g * EMB + tid] = ar / cnt;
        henv[g * EMB + tid] = ae / cnt;
        hout[g * EMB + tid] = ao / cnt;
    }
    __shared__ float sh[512];
    float gs = 0.f;
    for (int n = s + tid; n < e; n += blockDim.x) gs += gate[n];
    sh[tid] = gs;
    __syncthreads();
    for (int o = 256; o; o >>= 1) {
        if (tid < o) sh[tid] += sh[tid + o];
        __syncthreads();
    }
    if (tid == 0) {
        rnum[g] = sh[0] + 1e-8f;
        envnum[g] = ((float)(e - s) - sh[0]) + 1e-8f;
    }
}

// ---------------- per-graph norms + diagonal dot ----------------
__global__ void norm_kernel(const float* __restrict__ hr, const float* __restrict__ henv,
                            const float* __restrict__ hout, float* __restrict__ na,
                            float* __restrict__ nb, float* __restrict__ nc,
                            float* __restrict__ posdot) {
    int g = blockIdx.x, tid = threadIdx.x;
    float s1 = 0, s2 = 0, s3 = 0, s4 = 0;
    for (int d = tid; d < EMB; d += 128) {
        float a = hr[g * EMB + d], o = hout[g * EMB + d], ev = henv[g * EMB + d];
        s1 = fmaf(a, a, s1); s2 = fmaf(o, o, s2); s3 = fmaf(ev, ev, s3); s4 = fmaf(a, o, s4);
    }
    __shared__ float sh[128];
    auto red = [&](float v) -> float {
        sh[tid] = v; __syncthreads();
        for (int o = 64; o; o >>= 1) { if (tid < o) sh[tid] += sh[tid + o]; __syncthreads(); }
        float r = sh[0]; __syncthreads();
        return r;
    };
    float r1 = red(s1), r2 = red(s2), r3 = red(s3), r4 = red(s4);
    if (tid == 0) {
        na[g] = sqrtf(r1); nb[g] = sqrtf(r2); nc[g] = sqrtf(r3); posdot[g] = r4;
    }
}

__global__ void lossreg_kernel(const float* __restrict__ rnum, const float* __restrict__ envnum,
                               float* __restrict__ out) {
    int tid = threadIdx.x;
    float local = 0.f;
    for (int g = tid; g < GG; g += 512) {
        float r = rnum[g], ev = envnum[g];
        local += fabsf(r / (r + ev) - GAMMA);
    }
    __shared__ float sh[512];
    sh[tid] = local; __syncthreads();
    for (int o = 256; o; o >>= 1) { if (tid < o) sh[tid] += sh[tid + o]; __syncthreads(); }
    if (tid == 0) out[0] = sh[0] / (float)GG;
}

__global__ void transpose_kernel(const float* __restrict__ henv, float* __restrict__ henvT) {
    int idx = blockIdx.x * blockDim.x + threadIdx.x;
    if (idx >= GG * EMB) return;
    int g = idx / EMB, d = idx % EMB;
    henvT[d * GG + g] = henv[idx];
}

__global__ void rowsum_kernel(const float* __restrict__ S, const float* __restrict__ na,
                              const float* __restrict__ nc, float* __restrict__ rowsum) {
    int g = blockIdx.x, tid = threadIdx.x;
    float nag = na[g];
    float local = 0.f;
    for (int j = tid; j < GG; j += 256) {
        float denom = nag * nc[j] + 1e-8f;
        local += expf(S[(size_t)g * GG + j] / denom * INV_T);
    }
    __shared__ float sh[256];
    sh[tid] = local; __syncthreads();
    for (int o = 128; o; o >>= 1) { if (tid < o) sh[tid] += sh[tid + o]; __syncthreads(); }
    if (tid == 0) rowsum[g] = sh[0];
}

__global__ void losscon_kernel(const float* __restrict__ posdot, const float* __restrict__ na,
                               const float* __restrict__ nb, const float* __restrict__ rowsum,
                               float* __restrict__ out) {
    int tid = threadIdx.x;
    float local = 0.f;
    for (int g = tid; g < GG; g += 512) {
        float pos = expf(posdot[g] / (na[g] * nb[g] + 1e-8f) * INV_T);
        local += -logf(pos / (rowsum[g] + pos));
    }
    __shared__ float sh[512];
    sh[tid] = local; __syncthreads();
    for (int o = 256; o; o >>= 1) { if (tid < o) sh[tid] += sh[tid + o]; __syncthreads(); }
    if (tid == 0) out[0] = sh[0] / (float)GG;
}

__global__ void hin_kernel(const float* __restrict__ hr, const float* __restrict__ henv,
                           const int* __restrict__ perm, float* __restrict__ hin) {
    int idx = blockIdx.x * blockDim.x + threadIdx.x;
    if (idx >= GG * EMB) return;
    int g = idx / EMB, d = idx % EMB;
    float r = hr[idx];
    hin[idx] = r + henv[(size_t)perm[g] * EMB + d];
    hin[(size_t)(GG + g) * EMB + d] = r;
}

__global__ void pred2_kernel(const float* __restrict__ tmp, const float* __restrict__ Wp2,
                             const float* __restrict__ bp2, float* __restrict__ out) {
    int idx = blockIdx.x * blockDim.x + threadIdx.x;
    if (idx >= 2 * GG * TASKS) return;
    int row = idx / TASKS, t = idx % TASKS;
    const float* r = tmp + (size_t)row * EMB2;
    float acc = bp2[t];
    for (int k = 0; k < EMB2; k++) acc = fmaf(r[k], Wp2[k * TASKS + t], acc);
    int o = (row < GG) ? (row * TASKS + t) : (GG * TASKS + (row - GG) * TASKS + t);
    out[o] = acc;
}

// =====================================================================================
extern "C" void kernel_launch(void* const* d_in, const int* in_sizes, int n_in,
                              void* d_out, int out_size) {
    const float* x         = (const float*)d_in[0];
    const float* edge_attr = (const float*)d_in[1];
    const int*   edge_index= (const int*)  d_in[2];
    const int*   batch     = (const int*)  d_in[3];
    const float* gumbel    = (const float*)d_in[4];
    const int*   perm      = (const int*)  d_in[5];
    const float* W_enc = (const float*)d_in[6];
    const float* b_enc = (const float*)d_in[7];
    const float* We_g  = (const float*)d_in[8];
    const float* be_g  = (const float*)d_in[9];
    const float* W1_g  = (const float*)d_in[10];
    const float* b1_g  = (const float*)d_in[11];
    const float* W2_g  = (const float*)d_in[12];
    const float* b2_g  = (const float*)d_in[13];
    const float* We_r  = (const float*)d_in[14];
    const float* be_r  = (const float*)d_in[15];
    const float* W1_r  = (const float*)d_in[16];
    const float* b1_r  = (const float*)d_in[17];
    const float* W2_r  = (const float*)d_in[18];
    const float* b2_r  = (const float*)d_in[19];
    const float* Wg1   = (const float*)d_in[20];
    const float* bg1   = (const float*)d_in[21];
    const float* Wg2   = (const float*)d_in[22];
    const float* bg2   = (const float*)d_in[23];
    const float* Wp1   = (const float*)d_in[24];
    const float* bp1   = (const float*)d_in[25];
    const float* Wp2   = (const float*)d_in[26];
    const float* bp2   = (const float*)d_in[27];
    float* out = (float*)d_out;

    const int* src = edge_index;
    const int* dst = edge_index + EE;

    float *xfeat, *hb, *xr, *agg, *tmp, *gate, *hr, *henv, *hout, *henvT, *S;
    float *na, *nb, *nc, *posdot, *rnum, *envnum, *rowsum, *hin;
    __nv_bfloat16 *AS, *tmpS, *WS1, *WS2;
    cudaGetSymbolAddress((void**)&xfeat, d_xfeat);
    cudaGetSymbolAddress((void**)&hb, d_hb);
    cudaGetSymbolAddress((void**)&xr, d_xr);
    cudaGetSymbolAddress((void**)&agg, d_agg);
    cudaGetSymbolAddress((void**)&tmp, d_tmp);
    cudaGetSymbolAddress((void**)&gate, d_gate);
    cudaGetSymbolAddress((void**)&hr, d_hr);
    cudaGetSymbolAddress((void**)&henv, d_henv);
    cudaGetSymbolAddress((void**)&hout, d_hout);
    cudaGetSymbolAddress((void**)&henvT, d_henvT);
    cudaGetSymbolAddress((void**)&S, d_S);
    cudaGetSymbolAddress((void**)&na, d_na);
    cudaGetSymbolAddress((void**)&nb, d_nb);
    cudaGetSymbolAddress((void**)&nc, d_nc);
    cudaGetSymbolAddress((void**)&posdot, d_posdot);
    cudaGetSymbolAddress((void**)&rnum, d_rnum);
    cudaGetSymbolAddress((void**)&envnum, d_envnum);
    cudaGetSymbolAddress((void**)&rowsum, d_rowsum);
    cudaGetSymbolAddress((void**)&hin, d_hin);
    cudaGetSymbolAddress((void**)&AS, d_AS);
    cudaGetSymbolAddress((void**)&tmpS, d_tmpS);
    cudaGetSymbolAddress((void**)&WS1, d_WS1);
    cudaGetSymbolAddress((void**)&WS2, d_WS2);

    const size_t rowBytes = (size_t)NN * EMB * sizeof(float);

    enc_kernel<<<(NN * EMB + 255) / 256, 256>>>(x, W_enc, b_enc, xfeat);
    cudaMemcpyAsync(hb, xfeat, rowBytes, cudaMemcpyDeviceToDevice);
    cudaMemcpyAsync(xr, xfeat, rowBytes, cudaMemcpyDeviceToDevice);

    const int edgeBlocks = (EE + 7) / 8;
    dim3 gridG1(5, (NN + HBM - 1) / HBM);   // N=600
    dim3 gridG2(3, (NN + HBM - 1) / HBM);   // N=300
    const int splitABlocks = (NN * 304 + 255) / 256;
    const int splitW1Blocks = (300 * 600 + 255) / 256;
    const int splitW2Blocks = (600 * 304 + 255) / 256;

    // enc GIN stack (L=5)
    for (int l = 0; l < 5; l++) {
        cudaMemcpyAsync(agg, hb, rowBytes, cudaMemcpyDeviceToDevice);
        edge_mp<<<edgeBlocks, 256>>>(hb, agg, src, dst, edge_attr,
                                     We_g + l * 3 * EMB, be_g + l * EMB);
        splitW_kernel<<<splitW1Blocks, 256>>>(W1_g + (size_t)l * EMB * EMB2, 300, 600, 600, WS1);
        splitW_kernel<<<splitW2Blocks, 256>>>(W2_g + (size_t)l * EMB2 * EMB, 600, 300, 304, WS2);
        splitA_kernel<<<splitABlocks, 256>>>(agg, NN, AS);
        hgemm<<<gridG1, 256>>>(AS, KP3, WS1, 600, b1_g + l * EMB2,
                               nullptr, nullptr, tmpS, KP6, NN, 600, 900, 4);
        hgemm<<<gridG2, 256>>>(tmpS, KP6, WS2, 304, b2_g + l * EMB,
                               hb, hb, nullptr, 0, NN, 300, 1800, (l < 4) ? 1 : 2);
    }
    // rat GIN stack (L=2)
    for (int l = 0; l < 2; l++) {
        cudaMemcpyAsync(agg, xr, rowBytes, cudaMemcpyDeviceToDevice);
        edge_mp<<<edgeBlocks, 256>>>(xr, agg, src, dst, edge_attr,
                                     We_r + l * 3 * EMB, be_r + l * EMB);
        splitW_kernel<<<splitW1Blocks, 256>>>(W1_r + (size_t)l * EMB * EMB2, 300, 600, 600, WS1);
        splitW_kernel<<<splitW2Blocks, 256>>>(W2_r + (size_t)l * EMB2 * EMB, 600, 300, 304, WS2);
        splitA_kernel<<<splitABlocks, 256>>>(agg, NN, AS);
        hgemm<<<gridG1, 256>>>(AS, KP3, WS1, 600, b1_r + l * EMB2,
                               nullptr, nullptr, tmpS, KP6, NN, 600, 900, 4);
        hgemm<<<gridG2, 256>>>(tmpS, KP6, WS2, 304, b2_r + l * EMB,
                               xr, xr, nullptr, 0, NN, 300, 1800, (l < 1) ? 1 : 2);
    }

    // gate: tmp = relu(xr @ Wg1 + bg1)
    splitW_kernel<<<splitW1Blocks, 256>>>(Wg1, 300, 600, 600, WS1);
    splitA_kernel<<<splitABlocks, 256>>>(xr, NN, AS);
    hgemm<<<gridG1, 256>>>(AS, KP3, WS1, 600, bg1, tmp, nullptr, nullptr, 0,
                           NN, 600, 900, 0);
    gate_kernel<<<(NN * 32 + 255) / 256, 256>>>(tmp, Wg2, bg2, gumbel, gate);

    // per-graph reductions
    segment_kernel<<<GG, 512>>>(hb, gate, batch, hr, henv, hout, rnum, envnum);
    norm_kernel<<<GG, 128>>>(hr, henv, hout, na, nb, nc, posdot);
    lossreg_kernel<<<1, 512>>>(rnum, envnum, out + 2 * GG * TASKS);

    // contrastive loss: S = hr @ henv^T (fp32: feeds exp(5*cos))
    transpose_kernel<<<(GG * EMB + 255) / 256, 256>>>(henv, henvT);
    dim3 gridS((GG + BN - 1) / BN, (GG + BM - 1) / BM);
    sgemm_opt<<<gridS, 256>>>(hr, henvT, nullptr, S, nullptr, GG, GG, EMB, 3);
    rowsum_kernel<<<GG, 256>>>(S, na, nc, rowsum);
    losscon_kernel<<<1, 512>>>(posdot, na, nb, rowsum, out + 2 * GG * TASKS + 1);

    // prediction MLPs
    hin_kernel<<<(GG * EMB + 255) / 256, 256>>>(hr, henv, perm, hin);
    splitW_kernel<<<splitW1Blocks, 256>>>(Wp1, 300, 600, 600, WS1);
    splitA_kernel<<<(2 * GG * 304 + 255) / 256, 256>>>(hin, 2 * GG, AS);
    dim3 gridP(5, (2 * GG + HBM - 1) / HBM);
    hgemm<<<gridP, 256>>>(AS, KP3, WS1, 600, bp1, tmp, nullptr, nullptr, 0,
                          2 * GG, 600, 900, 0);
    pred2_kernel<<<(2 * GG * TASKS + 127) / 128, 128>>>(tmp, Wp2, bp2, out);
}

// round 8
// speedup vs baseline: 1.8062x; 1.0378x over previous
#include <cuda_runtime.h>
#include <cuda_bf16.h>
#include <math.h>
#include <stdint.h>

#define NN 30000
#define EE 240000
#define GG 1500
#define EMB 300
#define EMB2 600
#define TASKS 12
#define GAMMA 0.4f
#define INV_T 5.0f   // 1 / T_CON

#define KP3 928      // padded 3*300 -> mult of 32 (29 stages)
#define KP6 1824     // padded 3*600 -> mult of 32 (57 stages)
#define NPAD1 640    // padded N=600 (B cols)
#define NPAD2 384    // padded N=300 (B cols)

// ---------------- scratch (static device allocations only; zero-initialized) ----------------
__device__ float d_xfeat[NN * EMB];
__device__ float d_hb[NN * EMB];
__device__ float d_xr[NN * EMB];
__device__ float d_agg[NN * EMB];
__device__ float d_tmp[NN * EMB2];
__device__ float d_gate[NN];
__device__ float d_hr[GG * EMB];
__device__ float d_henv[GG * EMB];
__device__ float d_hout[GG * EMB];
__device__ float d_henvT[EMB * GG];
__device__ float d_S[GG * GG];
__device__ float d_na[GG], d_nb[GG], d_nc[GG], d_posdot[GG];
__device__ float d_rnum[GG], d_envnum[GG];
__device__ float d_rowsum[GG];
__device__ float d_hin[2 * GG * EMB];
// stacked bf16 operands; pad rows/cols never written -> stay zero
__device__ __nv_bfloat16 d_AS[(size_t)NN * KP3];
__device__ __nv_bfloat16 d_tmpS[(size_t)NN * KP6];
__device__ __nv_bfloat16 d_WS1[(size_t)KP3 * NPAD1];
__device__ __nv_bfloat16 d_WS2[(size_t)KP6 * NPAD2];

// ---------------- node encoder ----------------
__global__ void enc_kernel(const float* __restrict__ x, const float* __restrict__ W,
                           const float* __restrict__ b, float* __restrict__ out) {
    int idx = blockIdx.x * blockDim.x + threadIdx.x;
    if (idx >= NN * EMB) return;
    int i = idx / EMB, j = idx % EMB;
    const float* xr = x + i * 9;
    float acc = b[j];
#pragma unroll
    for (int k = 0; k < 9; k++) acc += xr[k] * W[k * EMB + j];
    out[idx] = acc;
}

// ------------- edge message passing: agg[dst] += relu(x[src] + ea@We + be) -------------
__global__ void edge_mp(const float* __restrict__ x, float* __restrict__ agg,
                        const int* __restrict__ src, const int* __restrict__ dst,
                        const float* __restrict__ ea, const float* __restrict__ We,
                        const float* __restrict__ be) {
    int w = (blockIdx.x * blockDim.x + threadIdx.x) >> 5;
    int lane = threadIdx.x & 31;
    if (w >= EE) return;
    int s = src[w], d = dst[w];
    float a0 = ea[w * 3 + 0], a1 = ea[w * 3 + 1], a2 = ea[w * 3 + 2];
    const float* xs = x + (size_t)s * EMB;
    float* ag = agg + (size_t)d * EMB;
    for (int k = lane; k < EMB; k += 32) {
        float e = fmaf(a0, We[k], fmaf(a1, We[EMB + k], fmaf(a2, We[2 * EMB + k], be[k])));
        float m = xs[k] + e;
        m = m > 0.f ? m : 0.f;
        atomicAdd(&ag[k], m);
    }
}

// ---------------- splits: x = hi + lo (bf16 pair) ----------------
// A' row (K=300): [h 0..299 | l 300..599 | h 600..899]; 900..927 stays zero
__global__ void splitA_kernel(const float* __restrict__ in, int M,
                              __nv_bfloat16* __restrict__ out) {
    int idx = blockIdx.x * blockDim.x + threadIdx.x;
    if (idx >= M * 300) return;
    int m = idx / 300, q = idx % 300;
    float v = in[(size_t)m * 300 + q];
    __nv_bfloat16 h = __float2bfloat16(v);
    __nv_bfloat16 l = __float2bfloat16(v - __bfloat162float(h));
    __nv_bfloat16* row = out + (size_t)m * KP3;
    row[q] = h; row[300 + q] = l; row[600 + q] = h;
}

// B' [3K rows, Npad] k-major: segments [h; h; l]; pad rows/cols zero (write zeros for n>=N)
__global__ void splitW_kernel(const float* __restrict__ W, int K, int N, int Npad,
                              __nv_bfloat16* __restrict__ WS) {
    int idx = blockIdx.x * blockDim.x + threadIdx.x;
    if (idx >= 3 * K * Npad) return;
    int k3 = idx / Npad, n = idx % Npad;
    __nv_bfloat16 r = __float2bfloat16(0.f);
    if (n < N) {
        int seg = k3 / K, k = k3 % K;
        float v = W[(size_t)k * N + n];
        __nv_bfloat16 h = __float2bfloat16(v);
        r = (seg < 2) ? h : __float2bfloat16(v - __bfloat162float(h));
    }
    WS[(size_t)k3 * Npad + n] = r;
}

// ============================================================================
// bf16 HMMA GEMM, 3-stage cp.async ring, one __syncthreads per stage.
// C[M,N] = A'[M,lda] @ B'[K3,ldb]; tile 128x128x32; 8 warps (2x4), warp 64x32.
// ep: 0 = +bias,relu -> C ; 1 = +bias,relu,+resid ; 2 = +bias,+resid ;
//     4 = +bias,relu -> outS split [h|l|h] rows of ldS
// ============================================================================
#define HA_STR 40
#define HB_STR 136
#define HA_BYTES (128 * HA_STR * 2)                    // 10240
#define HSTAGE_BYTES (HA_BYTES + 32 * HB_STR * 2)      // 18944
#define HG_SMEM (3 * HSTAGE_BYTES)                     // 56832

__global__ __launch_bounds__(256, 2)
void hgemm(const __nv_bfloat16* __restrict__ A, int lda,
           const __nv_bfloat16* __restrict__ B, int ldb,
           const float* __restrict__ bias, float* __restrict__ C,
           const float* __restrict__ resid,
           __nv_bfloat16* __restrict__ outS, int ldS,
           int M, int N, int K3, int ep) {
    extern __shared__ char hsm[];

    const int tid = threadIdx.x;
    const int wid = tid >> 5, lane = tid & 31;
    const int grp = lane >> 2, tig = lane & 3;
    const int wm = (wid >> 2) * 64, wn = (wid & 3) * 32;
    const int lrow = lane & 15, lcol = (lane >> 4) * 8;

    const int row0 = blockIdx.y * 128;
    const int col0 = blockIdx.x * 128;

    const int nk = K3 / 32;

    auto loadTile = [&](int t) {
        char* stA = hsm + (t % 3) * HSTAGE_BYTES;
        char* stB = stA + HA_BYTES;
        const int kb = t * 32;
#pragma unroll
        for (int i = 0; i < 2; i++) {
            int c = tid * 2 + i;
            int ar = c >> 2, ak = (c & 3) * 8;
            int gr = row0 + ar;
            const __nv_bfloat16* gp = A + (size_t)(gr < M ? gr : M - 1) * lda + kb + ak;
            uint32_t sp = (uint32_t)__cvta_generic_to_shared(stA + (ar * HA_STR + ak) * 2);
            int sz = (gr < M) ? 16 : 0;
            asm volatile("cp.async.cg.shared.global [%0], [%1], 16, %2;"
                         :: "r"(sp), "l"(gp), "r"(sz) : "memory");
        }
#pragma unroll
        for (int i = 0; i < 2; i++) {
            int c = tid * 2 + i;
            int br = c >> 4, bn = (c & 15) * 8;
            const __nv_bfloat16* gp = B + (size_t)(kb + br) * ldb + col0 + bn;
            uint32_t sp = (uint32_t)__cvta_generic_to_shared(stB + (br * HB_STR + bn) * 2);
            asm volatile("cp.async.cg.shared.global [%0], [%1], 16, 16;"
                         :: "r"(sp), "l"(gp) : "memory");
        }
        asm volatile("cp.async.commit_group;" ::: "memory");
    };

    float acc[4][4][4];
#pragma unroll
    for (int i = 0; i < 4; i++)
#pragma unroll
        for (int j = 0; j < 4; j++)
#pragma unroll
            for (int q = 0; q < 4; q++) acc[i][j][q] = 0.f;

    loadTile(0);
    if (nk > 1) loadTile(1);

    for (int t = 0; t < nk; t++) {
        if (t + 1 < nk)
            asm volatile("cp.async.wait_group 1;" ::: "memory");
        else
            asm volatile("cp.async.wait_group 0;" ::: "memory");
        __syncthreads();
        if (t + 2 < nk) loadTile(t + 2);   // writes buffer consumed at t-1: safe after sync

        char* stA = hsm + (t % 3) * HSTAGE_BYTES;
        char* stB = stA + HA_BYTES;
        __nv_bfloat16* Asm = (__nv_bfloat16*)stA;
        __nv_bfloat16* Bsm = (__nv_bfloat16*)stB;
#pragma unroll
        for (int ks = 0; ks < 2; ks++) {
            const int k0 = ks * 16;
            uint32_t af[4][4], bf[4][2];
#pragma unroll
            for (int mt = 0; mt < 4; mt++) {
                uint32_t sa = (uint32_t)__cvta_generic_to_shared(
                    &Asm[(wm + mt * 16 + lrow) * HA_STR + k0 + lcol]);
                asm volatile(
                    "ldmatrix.sync.aligned.m8n8.x4.shared.b16 {%0,%1,%2,%3}, [%4];"
                    : "=r"(af[mt][0]), "=r"(af[mt][1]), "=r"(af[mt][2]), "=r"(af[mt][3])
                    : "r"(sa));
            }
#pragma unroll
            for (int ng = 0; ng < 2; ng++) {
                uint32_t sb = (uint32_t)__cvta_generic_to_shared(
                    &Bsm[(k0 + lrow) * HB_STR + wn + ng * 16 + lcol]);
                uint32_t r0, r1, r2, r3;
                asm volatile(
                    "ldmatrix.sync.aligned.m8n8.x4.trans.shared.b16 {%0,%1,%2,%3}, [%4];"
                    : "=r"(r0), "=r"(r1), "=r"(r2), "=r"(r3) : "r"(sb));
                bf[ng * 2][0] = r0; bf[ng * 2][1] = r1;
                bf[ng * 2 + 1][0] = r2; bf[ng * 2 + 1][1] = r3;
            }
#pragma unroll
            for (int mt = 0; mt < 4; mt++)
#pragma unroll
                for (int nt = 0; nt < 4; nt++)
                    asm volatile(
                        "mma.sync.aligned.m16n8k16.row.col.f32.bf16.bf16.f32 "
                        "{%0,%1,%2,%3}, {%4,%5,%6,%7}, {%8,%9}, {%0,%1,%2,%3};"
                        : "+f"(acc[mt][nt][0]), "+f"(acc[mt][nt][1]),
                          "+f"(acc[mt][nt][2]), "+f"(acc[mt][nt][3])
                        : "r"(af[mt][0]), "r"(af[mt][1]), "r"(af[mt][2]), "r"(af[mt][3]),
                          "r"(bf[nt][0]), "r"(bf[nt][1]));
        }
    }

    // epilogue
#pragma unroll
    for (int mt = 0; mt < 4; mt++) {
#pragma unroll
        for (int nt = 0; nt < 4; nt++) {
            int rA = row0 + wm + mt * 16 + grp;
            int cA = col0 + wn + nt * 8 + 2 * tig;
#pragma unroll
            for (int half = 0; half < 2; half++) {
                int r = rA + half * 8;
                if (r >= M) continue;
#pragma unroll
                for (int q = 0; q < 2; q++) {
                    int c = cA + q;
                    if (c >= N) continue;
                    float v = acc[mt][nt][half * 2 + q] + bias[c];
                    if (ep != 2) v = fmaxf(v, 0.f);
                    if (ep == 4) {
                        __nv_bfloat16 h = __float2bfloat16(v);
                        __nv_bfloat16 l = __float2bfloat16(v - __bfloat162float(h));
                        __nv_bfloat16* rowS = outS + (size_t)r * ldS;
                        rowS[c] = h; rowS[N + c] = l; rowS[2 * N + c] = h;
                    } else {
                        if (ep == 1 || ep == 2) v += resid[(size_t)r * N + c];
                        C[(size_t)r * N + c] = v;
                    }
                }
            }
        }
    }
}

// ---------------- fp32 SGEMM (S matrix only) ----------------
#define BM 128
#define BN 128
#define BK 16
__global__ __launch_bounds__(256, 2)
void sgemm_opt(const float* __restrict__ A, const float* __restrict__ B,
               float* __restrict__ C, int M, int N, int K) {
    __shared__ float As[2][BK][BM + 4];
    __shared__ float Bs[2][BK][BN];
    const int tid = threadIdx.x;
    const int row0 = blockIdx.y * BM;
    const int col0 = blockIdx.x * BN;
    const int tx = tid & 15, ty = tid >> 4;
    const int ar = tid >> 1, ak0 = (tid & 1) * 8;
    const int br = tid >> 5, bc = (tid & 31) * 4;
    float4 aReg[2], bReg[2];
    const int gr = row0 + ar;
    const bool arow_ok = (gr < M);
    const float* Arow = A + (size_t)gr * K;

    auto loadA = [&](int k0) {
#pragma unroll
        for (int v = 0; v < 2; v++) {
            int k = k0 + ak0 + v * 4;
            float4 t = make_float4(0.f, 0.f, 0.f, 0.f);
            if (arow_ok) {
                if (k + 3 < K) t = *(const float4*)(Arow + k);
                else {
                    float u[4] = {0.f, 0.f, 0.f, 0.f};
#pragma unroll
                    for (int q = 0; q < 4; q++) if (k + q < K) u[q] = Arow[k + q];
                    t = make_float4(u[0], u[1], u[2], u[3]);
                }
            }
            aReg[v] = t;
        }
    };
    auto loadB = [&](int k0) {
#pragma unroll
        for (int v = 0; v < 2; v++) {
            int k = k0 + br + v * 8;
            int c = col0 + bc;
            float4 t = make_float4(0.f, 0.f, 0.f, 0.f);
            if (k < K) {
                const float* Brow = B + (size_t)k * N;
                if (c + 3 < N) t = *(const float4*)(Brow + c);
                else {
                    float u[4] = {0.f, 0.f, 0.f, 0.f};
#pragma unroll
                    for (int q = 0; q < 4; q++) if (c + q < N) u[q] = Brow[c + q];
                    t = make_float4(u[0], u[1], u[2], u[3]);
                }
            }
            bReg[v] = t;
        }
    };
    auto storeAB = [&](int buf) {
#pragma unroll
        for (int v = 0; v < 2; v++) {
            As[buf][ak0 + v * 4 + 0][ar] = aReg[v].x;
            As[buf][ak0 + v * 4 + 1][ar] = aReg[v].y;
            As[buf][ak0 + v * 4 + 2][ar] = aReg[v].z;
            As[buf][ak0 + v * 4 + 3][ar] = aReg[v].w;
            *(float4*)&Bs[buf][br + v * 8][bc] = bReg[v];
        }
    };

    float acc[8][8] = {};
    const int nk = (K + BK - 1) / BK;
    loadA(0); loadB(0); storeAB(0);
    __syncthreads();
    for (int t = 0; t < nk; t++) {
        const int buf = t & 1;
        if (t + 1 < nk) { loadA((t + 1) * BK); loadB((t + 1) * BK); }
#pragma unroll
        for (int kk = 0; kk < BK; kk++) {
            float a[8], b[8];
            *(float4*)&a[0] = *(const float4*)&As[buf][kk][ty * 8];
            *(float4*)&a[4] = *(const float4*)&As[buf][kk][ty * 8 + 4];
            *(float4*)&b[0] = *(const float4*)&Bs[buf][kk][tx * 8];
            *(float4*)&b[4] = *(const float4*)&Bs[buf][kk][tx * 8 + 4];
#pragma unroll
            for (int i = 0; i < 8; i++)
#pragma unroll
                for (int j = 0; j < 8; j++) acc[i][j] = fmaf(a[i], b[j], acc[i][j]);
        }
        if (t + 1 < nk) { storeAB(buf ^ 1); __syncthreads(); }
    }
#pragma unroll
    for (int i = 0; i < 8; i++) {
        int r = row0 + ty * 8 + i;
        if (r >= M) continue;
#pragma unroll
        for (int j = 0; j < 8; j++) {
            int c = col0 + tx * 8 + j;
            if (c >= N) continue;
            C[(size_t)r * N + c] = acc[i][j];
        }
    }
}

// ---------------- gate ----------------
__global__ void gate_kernel(const float* __restrict__ tmp, const float* __restrict__ Wg2,
                            const float* __restrict__ bg2, const float* __restrict__ gumbel,
                            float* __restrict__ gate) {
    int w = (blockIdx.x * blockDim.x + threadIdx.x) >> 5;
    int lane = threadIdx.x & 31;
    if (w >= NN) return;
    const float* row = tmp + (size_t)w * EMB2;
    float a0 = 0.f, a1 = 0.f;
    for (int k = lane; k < EMB2; k += 32) {
        float v = row[k];
        a0 = fmaf(v, Wg2[2 * k + 0], a0);
        a1 = fmaf(v, Wg2[2 * k + 1], a1);
    }
    for (int o = 16; o; o >>= 1) {
        a0 += __shfl_down_sync(0xffffffffu, a0, o);
        a1 += __shfl_down_sync(0xffffffffu, a1, o);
    }
    if (lane == 0) {
        float z0 = a0 + bg2[0] + gumbel[2 * w + 0];
        float z1 = a1 + bg2[1] + gumbel[2 * w + 1];
        gate[w] = 1.f / (1.f + expf(z0 - z1));
    }
}

// ---------------- per-graph segment means (batch sorted) ----------------
__device__ __forceinline__ int lower_bound_batch(const int* __restrict__ batch, int val) {
    int lo = 0, hi = NN;
    while (lo < hi) {
        int mid = (lo + hi) >> 1;
        if (batch[mid] < val) lo = mid + 1; else hi = mid;
    }
    return lo;
}

__global__ void segment_kernel(const float* __restrict__ hb, const float* __restrict__ gate,
                               const int* __restrict__ batch,
                               float* __restrict__ hr, float* __restrict__ henv,
                               float* __restrict__ hout, float* __restrict__ rnum,
                               float* __restrict__ envnum) {
    int g = blockIdx.x;
    int s = lower_bound_batch(batch, g);
    int e = lower_bound_batch(batch, g + 1);
    float cnt = fmaxf((float)(e - s), 1.f);
    int tid = threadIdx.x;
    if (tid < EMB) {
        float ar = 0.f, ae = 0.f, ao = 0.f;
        for (int n = s; n < e; n++) {
            float h = hb[(size_t)n * EMB + tid];
            float gt = gate[n];
            ar = fmaf(gt, h, ar);
            ae = fmaf(1.f - gt, h, ae);
            ao += h;
        }
        hr[g * EMB + tid] = ar / cnt;
        henv[g * EMB + tid] = ae / cnt;
        hout[g * EMB + tid] = ao / cnt;
    }
    __shared__ float sh[512];
    float gs = 0.f;
    for (int n = s + tid; n < e; n += blockDim.x) gs += gate[n];
    sh[tid] = gs;
    __syncthreads();
    for (int o = 256; o; o >>= 1) {
        if (tid < o) sh[tid] += sh[tid + o];
        __syncthreads();
    }
    if (tid == 0) {
        rnum[g] = sh[0] + 1e-8f;
        envnum[g] = ((float)(e - s) - sh[0]) + 1e-8f;
    }
}

__global__ void norm_kernel(const float* __restrict__ hr, const float* __restrict__ henv,
                            const float* __restrict__ hout, float* __restrict__ na,
                            float* __restrict__ nb, float* __restrict__ nc,
                            float* __restrict__ posdot) {
    int g = blockIdx.x, tid = threadIdx.x;
    float s1 = 0, s2 = 0, s3 = 0, s4 = 0;
    for (int d = tid; d < EMB; d += 128) {
        float a = hr[g * EMB + d], o = hout[g * EMB + d], ev = henv[g * EMB + d];
        s1 = fmaf(a, a, s1); s2 = fmaf(o, o, s2); s3 = fmaf(ev, ev, s3); s4 = fmaf(a, o, s4);
    }
    __shared__ float sh[128];
    auto red = [&](float v) -> float {
        sh[tid] = v; __syncthreads();
        for (int o = 64; o; o >>= 1) { if (tid < o) sh[tid] += sh[tid + o]; __syncthreads(); }
        float r = sh[0]; __syncthreads();
        return r;
    };
    float r1 = red(s1), r2 = red(s2), r3 = red(s3), r4 = red(s4);
    if (tid == 0) {
        na[g] = sqrtf(r1); nb[g] = sqrtf(r2); nc[g] = sqrtf(r3); posdot[g] = r4;
    }
}

__global__ void lossreg_kernel(const float* __restrict__ rnum, const float* __restrict__ envnum,
                               float* __restrict__ out) {
    int tid = threadIdx.x;
    float local = 0.f;
    for (int g = tid; g < GG; g += 512) {
        float r = rnum[g], ev = envnum[g];
        local += fabsf(r / (r + ev) - GAMMA);
    }
    __shared__ float sh[512];
    sh[tid] = local; __syncthreads();
    for (int o = 256; o; o >>= 1) { if (tid < o) sh[tid] += sh[tid + o]; __syncthreads(); }
    if (tid == 0) out[0] = sh[0] / (float)GG;
}

__global__ void transpose_kernel(const float* __restrict__ henv, float* __restrict__ henvT) {
    int idx = blockIdx.x * blockDim.x + threadIdx.x;
    if (idx >= GG * EMB) return;
    int g = idx / EMB, d = idx % EMB;
    henvT[d * GG + g] = henv[idx];
}

__global__ void rowsum_kernel(const float* __restrict__ S, const float* __restrict__ na,
                              const float* __restrict__ nc, float* __restrict__ rowsum) {
    int g = blockIdx.x, tid = threadIdx.x;
    float nag = na[g];
    float local = 0.f;
    for (int j = tid; j < GG; j += 256) {
        float denom = nag * nc[j] + 1e-8f;
        local += expf(S[(size_t)g * GG + j] / denom * INV_T);
    }
    __shared__ float sh[256];
    sh[tid] = local; __syncthreads();
    for (int o = 128; o; o >>= 1) { if (tid < o) sh[tid] += sh[tid + o]; __syncthreads(); }
    if (tid == 0) rowsum[g] = sh[0];
}

__global__ void losscon_kernel(const float* __restrict__ posdot, const float* __restrict__ na,
                               const float* __restrict__ nb, const float* __restrict__ rowsum,
                               float* __restrict__ out) {
    int tid = threadIdx.x;
    float local = 0.f;
    for (int g = tid; g < GG; g += 512) {
        float pos = expf(posdot[g] / (na[g] * nb[g] + 1e-8f) * INV_T);
        local += -logf(pos / (rowsum[g] + pos));
    }
    __shared__ float sh[512];
    sh[tid] = local; __syncthreads();
    for (int o = 256; o; o >>= 1) { if (tid < o) sh[tid] += sh[tid + o]; __syncthreads(); }
    if (tid == 0) out[0] = sh[0] / (float)GG;
}

__global__ void hin_kernel(const float* __restrict__ hr, const float* __restrict__ henv,
                           const int* __restrict__ perm, float* __restrict__ hin) {
    int idx = blockIdx.x * blockDim.x + threadIdx.x;
    if (idx >= GG * EMB) return;
    int g = idx / EMB, d = idx % EMB;
    float r = hr[idx];
    hin[idx] = r + henv[(size_t)perm[g] * EMB + d];
    hin[(size_t)(GG + g) * EMB + d] = r;
}

__global__ void pred2_kernel(const float* __restrict__ tmp, const float* __restrict__ Wp2,
                             const float* __restrict__ bp2, float* __restrict__ out) {
    int idx = blockIdx.x * blockDim.x + threadIdx.x;
    if (idx >= 2 * GG * TASKS) return;
    int row = idx / TASKS, t = idx % TASKS;
    const float* r = tmp + (size_t)row * EMB2;
    float acc = bp2[t];
    for (int k = 0; k < EMB2; k++) acc = fmaf(r[k], Wp2[k * TASKS + t], acc);
    int o = (row < GG) ? (row * TASKS + t) : (GG * TASKS + (row - GG) * TASKS + t);
    out[o] = acc;
}

// =====================================================================================
extern "C" void kernel_launch(void* const* d_in, const int* in_sizes, int n_in,
                              void* d_out, int out_size) {
    const float* x         = (const float*)d_in[0];
    const float* edge_attr = (const float*)d_in[1];
    const int*   edge_index= (const int*)  d_in[2];
    const int*   batch     = (const int*)  d_in[3];
    const float* gumbel    = (const float*)d_in[4];
    const int*   perm      = (const int*)  d_in[5];
    const float* W_enc = (const float*)d_in[6];
    const float* b_enc = (const float*)d_in[7];
    const float* We_g  = (const float*)d_in[8];
    const float* be_g  = (const float*)d_in[9];
    const float* W1_g  = (const float*)d_in[10];
    const float* b1_g  = (const float*)d_in[11];
    const float* W2_g  = (const float*)d_in[12];
    const float* b2_g  = (const float*)d_in[13];
    const float* We_r  = (const float*)d_in[14];
    const float* be_r  = (const float*)d_in[15];
    const float* W1_r  = (const float*)d_in[16];
    const float* b1_r  = (const float*)d_in[17];
    const float* W2_r  = (const float*)d_in[18];
    const float* b2_r  = (const float*)d_in[19];
    const float* Wg1   = (const float*)d_in[20];
    const float* bg1   = (const float*)d_in[21];
    const float* Wg2   = (const float*)d_in[22];
    const float* bg2   = (const float*)d_in[23];
    const float* Wp1   = (const float*)d_in[24];
    const float* bp1   = (const float*)d_in[25];
    const float* Wp2   = (const float*)d_in[26];
    const float* bp2   = (const float*)d_in[27];
    float* out = (float*)d_out;

    const int* src = edge_index;
    const int* dst = edge_index + EE;

    float *xfeat, *hb, *xr, *agg, *tmp, *gate, *hr, *henv, *hout, *henvT, *S;
    float *na, *nb, *nc, *posdot, *rnum, *envnum, *rowsum, *hin;
    __nv_bfloat16 *AS, *tmpS, *WS1, *WS2;
    cudaGetSymbolAddress((void**)&xfeat, d_xfeat);
    cudaGetSymbolAddress((void**)&hb, d_hb);
    cudaGetSymbolAddress((void**)&xr, d_xr);
    cudaGetSymbolAddress((void**)&agg, d_agg);
    cudaGetSymbolAddress((void**)&tmp, d_tmp);
    cudaGetSymbolAddress((void**)&gate, d_gate);
    cudaGetSymbolAddress((void**)&hr, d_hr);
    cudaGetSymbolAddress((void**)&henv, d_henv);
    cudaGetSymbolAddress((void**)&hout, d_hout);
    cudaGetSymbolAddress((void**)&henvT, d_henvT);
    cudaGetSymbolAddress((void**)&S, d_S);
    cudaGetSymbolAddress((void**)&na, d_na);
    cudaGetSymbolAddress((void**)&nb, d_nb);
    cudaGetSymbolAddress((void**)&nc, d_nc);
    cudaGetSymbolAddress((void**)&posdot, d_posdot);
    cudaGetSymbolAddress((void**)&rnum, d_rnum);
    cudaGetSymbolAddress((void**)&envnum, d_envnum);
    cudaGetSymbolAddress((void**)&rowsum, d_rowsum);
    cudaGetSymbolAddress((void**)&hin, d_hin);
    cudaGetSymbolAddress((void**)&AS, d_AS);
    cudaGetSymbolAddress((void**)&tmpS, d_tmpS);
    cudaGetSymbolAddress((void**)&WS1, d_WS1);
    cudaGetSymbolAddress((void**)&WS2, d_WS2);

    cudaFuncSetAttribute(hgemm, cudaFuncAttributeMaxDynamicSharedMemorySize, HG_SMEM);

    const size_t rowBytes = (size_t)NN * EMB * sizeof(float);

    enc_kernel<<<(NN * EMB + 255) / 256, 256>>>(x, W_enc, b_enc, xfeat);
    cudaMemcpyAsync(hb, xfeat, rowBytes, cudaMemcpyDeviceToDevice);
    cudaMemcpyAsync(xr, xfeat, rowBytes, cudaMemcpyDeviceToDevice);

    const int edgeBlocks = (EE + 7) / 8;
    const int MT = (NN + 127) / 128;
    dim3 gridG1(NPAD1 / 128, MT);   // 5 x 235
    dim3 gridG2(NPAD2 / 128, MT);   // 3 x 235
    const int splitABlk = (NN * 300 + 255) / 256;
    const int splitW1Blk = (900 * NPAD1 + 255) / 256;
    const int splitW2Blk = (1800 * NPAD2 + 255) / 256;

    // enc GIN stack (L=5)
    for (int l = 0; l < 5; l++) {
        cudaMemcpyAsync(agg, hb, rowBytes, cudaMemcpyDeviceToDevice);
        edge_mp<<<edgeBlocks, 256>>>(hb, agg, src, dst, edge_attr,
                                     We_g + l * 3 * EMB, be_g + l * EMB);
        splitW_kernel<<<splitW1Blk, 256>>>(W1_g + (size_t)l * EMB * EMB2, 300, 600, NPAD1, WS1);
        splitW_kernel<<<splitW2Blk, 256>>>(W2_g + (size_t)l * EMB2 * EMB, 600, 300, NPAD2, WS2);
        splitA_kernel<<<splitABlk, 256>>>(agg, NN, AS);
        hgemm<<<gridG1, 256, HG_SMEM>>>(AS, KP3, WS1, NPAD1, b1_g + l * EMB2,
                                        nullptr, nullptr, tmpS, KP6, NN, 600, KP3, 4);
        hgemm<<<gridG2, 256, HG_SMEM>>>(tmpS, KP6, WS2, NPAD2, b2_g + l * EMB,
                                        hb, hb, nullptr, 0, NN, 300, KP6, (l < 4) ? 1 : 2);
    }
    // rat GIN stack (L=2)
    for (int l = 0; l < 2; l++) {
        cudaMemcpyAsync(agg, xr, rowBytes, cudaMemcpyDeviceToDevice);
        edge_mp<<<edgeBlocks, 256>>>(xr, agg, src, dst, edge_attr,
                                     We_r + l * 3 * EMB, be_r + l * EMB);
        splitW_kernel<<<splitW1Blk, 256>>>(W1_r + (size_t)l * EMB * EMB2, 300, 600, NPAD1, WS1);
        splitW_kernel<<<splitW2Blk, 256>>>(W2_r + (size_t)l * EMB2 * EMB, 600, 300, NPAD2, WS2);
        splitA_kernel<<<splitABlk, 256>>>(agg, NN, AS);
        hgemm<<<gridG1, 256, HG_SMEM>>>(AS, KP3, WS1, NPAD1, b1_r + l * EMB2,
                                        nullptr, nullptr, tmpS, KP6, NN, 600, KP3, 4);
        hgemm<<<gridG2, 256, HG_SMEM>>>(tmpS, KP6, WS2, NPAD2, b2_r + l * EMB,
                                        xr, xr, nullptr, 0, NN, 300, KP6, (l < 1) ? 1 : 2);
    }

    // gate: tmp = relu(xr @ Wg1 + bg1)
    splitW_kernel<<<splitW1Blk, 256>>>(Wg1, 300, 600, NPAD1, WS1);
    splitA_kernel<<<splitABlk, 256>>>(xr, NN, AS);
    hgemm<<<gridG1, 256, HG_SMEM>>>(AS, KP3, WS1, NPAD1, bg1, tmp, nullptr, nullptr, 0,
                                    NN, 600, KP3, 0);
    gate_kernel<<<(NN * 32 + 255) / 256, 256>>>(tmp, Wg2, bg2, gumbel, gate);

    // per-graph reductions
    segment_kernel<<<GG, 512>>>(hb, gate, batch, hr, henv, hout, rnum, envnum);
    norm_kernel<<<GG, 128>>>(hr, henv, hout, na, nb, nc, posdot);
    lossreg_kernel<<<1, 512>>>(rnum, envnum, out + 2 * GG * TASKS);

    // contrastive loss: S = hr @ henv^T (fp32: feeds exp(5*cos))
    transpose_kernel<<<(GG * EMB + 255) / 256, 256>>>(henv, henvT);
    dim3 gridS((GG + BN - 1) / BN, (GG + BM - 1) / BM);
    sgemm_opt<<<gridS, 256>>>(hr, henvT, S, GG, GG, EMB);
    rowsum_kernel<<<GG, 256>>>(S, na, nc, rowsum);
    losscon_kernel<<<1, 512>>>(posdot, na, nb, rowsum, out + 2 * GG * TASKS + 1);

    // prediction MLPs
    hin_kernel<<<(GG * EMB + 255) / 256, 256>>>(hr, henv, perm, hin);
    splitW_kernel<<<splitW1Blk, 256>>>(Wp1, 300, 600, NPAD1, WS1);
    splitA_kernel<<<(2 * GG * 300 + 255) / 256, 256>>>(hin, 2 * GG, AS);
    dim3 gridP(NPAD1 / 128, (2 * GG + 127) / 128);
    hgemm<<<gridP, 256, HG_SMEM>>>(AS, KP3, WS1, NPAD1, bp1, tmp, nullptr, nullptr, 0,
                                   2 * GG, 600, KP3, 0);
    pred2_kernel<<<(2 * GG * TASKS + 127) / 128, 128>>>(tmp, Wp2, bp2, out);
}